// round 5
// baseline (speedup 1.0000x reference)
#include <cuda_runtime.h>
#include <math.h>

// ---------------- problem constants ----------------
#define BATCH 2
#define SEQ   1024
#define DIM   1024
#define HDIM  256
#define MBITS 32
#define NTOK  (BATCH*SEQ)     // 2048
#define PROJ  192             // 6 groups x 32
#define SCALEF 0.17677669529663687f  // 1/sqrt(32)

typedef unsigned long long ull;

// ---------------- device scratch (static, no allocs) ----------------
__device__ float    g_Wq[PROJ*DIM];
__device__ float    g_Wk[PROJ*DIM];
__device__ float    g_Bq[PROJ];
__device__ float    g_Bk[PROJ];
__device__ float    g_Wv[4*HDIM*DIM];
__device__ float    g_qproj[NTOK*PROJ];
__device__ float    g_kproj[NTOK*PROJ];
__device__ unsigned g_qbits[NTOK*2];
__device__ unsigned g_kbits[NTOK*2];
__device__ float    g_Vp[NTOK*4*HDIM];
__device__ float    g_cat[NTOK*4*HDIM];

// ---------------- pack weights into fused layouts ----------------
__global__ void pack_weights(
    const float* __restrict__ bq_w, const float* __restrict__ tq_w,
    const float* __restrict__ rq_w, const float* __restrict__ pq_w,
    const float* __restrict__ bq_b, const float* __restrict__ tq_b,
    const float* __restrict__ rq_b, const float* __restrict__ pq_b,
    const float* __restrict__ bk_w, const float* __restrict__ tk_w,
    const float* __restrict__ rk_w, const float* __restrict__ pk_w,
    const float* __restrict__ bk_b, const float* __restrict__ tk_b,
    const float* __restrict__ rk_b, const float* __restrict__ pk_b,
    const float* __restrict__ b_v,  const float* __restrict__ t_v,
    const float* __restrict__ r_v,  const float* __restrict__ p_v)
{
    int i0 = blockIdx.x * blockDim.x + threadIdx.x;
    int stride = gridDim.x * blockDim.x;
    for (int e = i0; e < 4*HDIM*DIM; e += stride) {
        int h = e >> 10, d = e & 1023;
        float v;
        if (h < 256)      v = b_v[h*DIM + d];
        else if (h < 512) v = t_v[(h-256)*DIM + d];
        else if (h < 768) v = r_v[(h-512)*DIM + d];
        else              v = p_v[(h-768)*DIM + d];
        g_Wv[e] = v;
    }
    for (int e = i0; e < PROJ*DIM; e += stride) {
        int r = e >> 10, d = e & 1023;
        int g = r >> 5, j = r & 31;
        const float* sq; const float* sk;
        switch (g) {
            case 0: sq = bq_w; sk = bk_w; break;
            case 1: sq = tq_w; sk = tk_w; break;
            case 2: sq = rq_w; sk = rk_w; break;
            default: sq = pq_w + (g-3)*MBITS*DIM; sk = pk_w + (g-3)*MBITS*DIM; break;
        }
        int off = j*DIM + d;
        g_Wq[e] = sq[off];
        g_Wk[e] = sk[off];
    }
    for (int e = i0; e < PROJ; e += stride) {
        int g = e >> 5, j = e & 31;
        float vq, vk;
        switch (g) {
            case 0: vq = bq_b[j]; vk = bk_b[j]; break;
            case 1: vq = tq_b[j]; vk = tk_b[j]; break;
            case 2: vq = rq_b[j]; vk = rk_b[j]; break;
            default: vq = pq_b[(g-3)*MBITS + j]; vk = pk_b[(g-3)*MBITS + j]; break;
        }
        g_Bq[e] = vq;
        g_Bk[e] = vk;
    }
}

// ---------------- fp32 double-buffered GEMM (exact QK projections) ----------
template<int BM, int TM>
__global__ __launch_bounds__(256) void gemm_db(
    const float* __restrict__ A0, const float* __restrict__ A1,
    const float* __restrict__ W0, const float* __restrict__ W1,
    const float* __restrict__ b0, const float* __restrict__ b1,
    float* __restrict__ C0, float* __restrict__ C1,
    int M, int N, int K)
{
    __shared__ __align__(16) float As[2][8][BM+4];
    __shared__ __align__(16) float Ws[2][8][132];

    const float* A    = blockIdx.z ? A1 : A0;
    const float* W    = blockIdx.z ? W1 : W0;
    const float* bias = blockIdx.z ? b1 : b0;
    float*       C    = blockIdx.z ? C1 : C0;

    const int bm = blockIdx.y * BM, bn = blockIdx.x * 128;
    const int tid = threadIdx.x;
    const int tx = tid & 15, ty = tid >> 4;
    const int lrow = tid >> 1, lc4 = (tid & 1) * 4;

    const bool aact = (tid < BM*2);
    const bool wact = (bn + lrow) < N;
    const float* Aptr = A + (size_t)(bm + lrow)*K + lc4;
    const float* Wptr = W + (size_t)(bn + lrow)*K + lc4;

    float acc[TM][8];
    #pragma unroll
    for (int i = 0; i < TM; ++i)
        #pragma unroll
        for (int j = 0; j < 8; ++j) acc[i][j] = 0.f;

    const int nt = K >> 3;
    float4 areg = make_float4(0,0,0,0), wreg = make_float4(0,0,0,0);
    if (aact) areg = *(const float4*)Aptr;
    if (wact) wreg = *(const float4*)Wptr;
    #pragma unroll
    for (int j = 0; j < 4; ++j) {
        if (aact) As[0][lc4+j][lrow] = (&areg.x)[j];
        Ws[0][lc4+j][lrow] = (&wreg.x)[j];
    }
    __syncthreads();

    for (int t = 0; t < nt; ++t) {
        const int cur = t & 1;
        if (t + 1 < nt) {
            if (aact) areg = *(const float4*)(Aptr + (t+1)*8);
            if (wact) wreg = *(const float4*)(Wptr + (t+1)*8);
        }
        #pragma unroll
        for (int kk = 0; kk < 8; ++kk) {
            float a[TM], b[8];
            *(float4*)&b[0] = *(const float4*)&Ws[cur][kk][tx*8];
            *(float4*)&b[4] = *(const float4*)&Ws[cur][kk][tx*8+4];
            *(float4*)&a[0] = *(const float4*)&As[cur][kk][ty*TM];
            if (TM == 8) *(float4*)&a[4] = *(const float4*)&As[cur][kk][ty*TM+4];
            #pragma unroll
            for (int i = 0; i < TM; ++i)
                #pragma unroll
                for (int j = 0; j < 8; ++j)
                    acc[i][j] += a[i]*b[j];
        }
        if (t + 1 < nt) {
            const int nxt = cur ^ 1;
            #pragma unroll
            for (int j = 0; j < 4; ++j) {
                if (aact) As[nxt][lc4+j][lrow] = (&areg.x)[j];
                Ws[nxt][lc4+j][lrow] = (&wreg.x)[j];
            }
        }
        __syncthreads();
    }

    #pragma unroll
    for (int i = 0; i < TM; ++i) {
        int row = bm + ty*TM + i;
        #pragma unroll
        for (int j4 = 0; j4 < 2; ++j4) {
            int col = bn + tx*8 + j4*4;
            if (col < N) {
                float4 o;
                o.x = acc[i][j4*4+0]; o.y = acc[i][j4*4+1];
                o.z = acc[i][j4*4+2]; o.w = acc[i][j4*4+3];
                if (bias) { o.x += bias[col]; o.y += bias[col+1]; o.z += bias[col+2]; o.w += bias[col+3]; }
                *(float4*)&C[(size_t)row*N + col] = o;
            }
        }
    }
}

// ---------------- tf32 / packed-f32x2 helpers ----------------
__device__ __forceinline__ unsigned f2tf32(float f) {
    unsigned u;
    asm("cvt.rna.tf32.f32 %0, %1;" : "=r"(u) : "f"(f));
    return u;
}
__device__ __forceinline__ void mma_tf32(float c[4],
    unsigned a0, unsigned a1, unsigned a2, unsigned a3,
    unsigned b0, unsigned b1)
{
    asm("mma.sync.aligned.m16n8k8.row.col.f32.tf32.tf32.f32 "
        "{%0,%1,%2,%3},{%4,%5,%6,%7},{%8,%9},{%0,%1,%2,%3};"
        : "+f"(c[0]), "+f"(c[1]), "+f"(c[2]), "+f"(c[3])
        : "r"(a0), "r"(a1), "r"(a2), "r"(a3), "r"(b0), "r"(b1));
}
__device__ __forceinline__ ull fadd2(ull a, ull b) {
    ull r; asm("add.rn.f32x2 %0,%1,%2;" : "=l"(r) : "l"(a), "l"(b)); return r;
}
__device__ __forceinline__ ull ffma2(ull a, ull b, ull c) {
    ull r; asm("fma.rn.f32x2 %0,%1,%2,%3;" : "=l"(r) : "l"(a), "l"(b), "l"(c)); return r;
}
__device__ __forceinline__ float ulo(ull x) { return __uint_as_float((unsigned)x); }
__device__ __forceinline__ float uhi(ull x) { return __uint_as_float((unsigned)(x >> 32)); }

// ---------------- tf32 tensor-core GEMM (V-proj, out-proj) ----------------
__global__ __launch_bounds__(256) void gemm_tc(
    const float* __restrict__ A, const float* __restrict__ W,
    const float* __restrict__ bias, float* __restrict__ C,
    int M, int N, int K)
{
    __shared__ unsigned As[2][8][136];
    __shared__ unsigned Ws[2][8][136];

    const int bm = blockIdx.y * 128, bn = blockIdx.x * 128;
    const int tid = threadIdx.x;
    const int w = tid >> 5, lane = tid & 31;
    const int wm = w >> 2, wn = w & 3;
    const int qr = lane >> 2, qc = lane & 3;
    const int lrow = tid >> 1, lc4 = (tid & 1) * 4;

    const float* Aptr = A + (size_t)(bm + lrow)*K + lc4;
    const float* Wptr = W + (size_t)(bn + lrow)*K + lc4;

    float acc[4][4][4];
    #pragma unroll
    for (int i = 0; i < 4; ++i)
        #pragma unroll
        for (int j = 0; j < 4; ++j)
            #pragma unroll
            for (int r = 0; r < 4; ++r) acc[i][j][r] = 0.f;

    const int nt = K >> 3;
    float4 areg = *(const float4*)Aptr;
    float4 wreg = *(const float4*)Wptr;
    #pragma unroll
    for (int j = 0; j < 4; ++j) {
        As[0][lc4+j][lrow] = f2tf32((&areg.x)[j]);
        Ws[0][lc4+j][lrow] = f2tf32((&wreg.x)[j]);
    }
    __syncthreads();

    for (int t = 0; t < nt; ++t) {
        const int cur = t & 1;
        if (t + 1 < nt) {
            areg = *(const float4*)(Aptr + (t+1)*8);
            wreg = *(const float4*)(Wptr + (t+1)*8);
        }
        unsigned af[4][4], bf[4][2];
        #pragma unroll
        for (int i = 0; i < 4; ++i) {
            int m0 = wm*64 + i*16 + qr;
            af[i][0] = As[cur][qc  ][m0];
            af[i][1] = As[cur][qc  ][m0+8];
            af[i][2] = As[cur][qc+4][m0];
            af[i][3] = As[cur][qc+4][m0+8];
        }
        #pragma unroll
        for (int j = 0; j < 4; ++j) {
            int n0 = wn*32 + j*8 + qr;
            bf[j][0] = Ws[cur][qc  ][n0];
            bf[j][1] = Ws[cur][qc+4][n0];
        }
        #pragma unroll
        for (int i = 0; i < 4; ++i)
            #pragma unroll
            for (int j = 0; j < 4; ++j)
                mma_tf32(acc[i][j], af[i][0], af[i][1], af[i][2], af[i][3],
                         bf[j][0], bf[j][1]);
        if (t + 1 < nt) {
            const int nxt = cur ^ 1;
            #pragma unroll
            for (int j = 0; j < 4; ++j) {
                As[nxt][lc4+j][lrow] = f2tf32((&areg.x)[j]);
                Ws[nxt][lc4+j][lrow] = f2tf32((&wreg.x)[j]);
            }
        }
        __syncthreads();
    }

    #pragma unroll
    for (int i = 0; i < 4; ++i) {
        int r0 = bm + wm*64 + i*16 + qr;
        #pragma unroll
        for (int j = 0; j < 4; ++j) {
            int c0 = bn + wn*32 + j*8 + 2*qc;
            float bx = 0.f, by = 0.f;
            if (bias) { bx = bias[c0]; by = bias[c0+1]; }
            float2 o0, o1;
            o0.x = acc[i][j][0] + bx; o0.y = acc[i][j][1] + by;
            o1.x = acc[i][j][2] + bx; o1.y = acc[i][j][3] + by;
            *(float2*)&C[(size_t)r0*N + c0]     = o0;
            *(float2*)&C[(size_t)(r0+8)*N + c0] = o1;
        }
    }
}

// ---------------- bit packing for boolean heads ----------------
__global__ void pack_bits()
{
    int gw = (blockIdx.x * blockDim.x + threadIdx.x) >> 5;
    int lane = threadIdx.x & 31;
    if (gw >= NTOK) return;
    unsigned q0 = __ballot_sync(0xffffffffu, g_qproj[(size_t)gw*PROJ + lane]       > 0.f);
    unsigned q1 = __ballot_sync(0xffffffffu, g_qproj[(size_t)gw*PROJ + 96 + lane]  > 0.f);
    unsigned k0 = __ballot_sync(0xffffffffu, g_kproj[(size_t)gw*PROJ + lane]       > 0.f);
    unsigned k1 = __ballot_sync(0xffffffffu, g_kproj[(size_t)gw*PROJ + 96 + lane]  > 0.f);
    if (lane == 0) {
        g_qbits[gw*2]   = q0; g_qbits[gw*2+1] = q1;
        g_kbits[gw*2]   = k0; g_kbits[gw*2+1] = k1;
    }
}

// ---------------- fused attention: 64 q x 1 head per block, 512 threads ----
__device__ __forceinline__ float wredmax(float v) {
    #pragma unroll
    for (int o = 16; o; o >>= 1) v = fmaxf(v, __shfl_xor_sync(0xffffffffu, v, o));
    return v;
}
__device__ __forceinline__ float wredsum(float v) {
    #pragma unroll
    for (int o = 16; o; o >>= 1) v += __shfl_xor_sync(0xffffffffu, v, o);
    return v;
}

#define VP_STRIDE 264
#define SC_STRIDE 68
#define ENC_STRIDE 72   // floats per encoding row: 16 m-pairs x (e0lo,e0hi,e1lo,e1hi)
// floats: vp 64*264 | sc 64*68 | qeC 64*72 | keC 64*72 | msm,lsm,cf 192 | qb,kb 128
#define ATTN_SMEM_FLOATS (64*VP_STRIDE + 64*SC_STRIDE + 2*64*ENC_STRIDE + 192 + 128)
#define ATTN_SMEM_BYTES  (ATTN_SMEM_FLOATS*4)

__global__ __launch_bounds__(512) void attn_kernel(const float* __restrict__ t_temp,
                                                   const float* __restrict__ p_fusion)
{
    extern __shared__ __align__(16) float sm[];
    float* vp  = sm;                          // [64][264] tf32 bits
    float* sc  = vp + 64*VP_STRIDE;           // [64][68]
    float* qeC = sc + 64*SC_STRIDE;           // [64][72] interleaved encodings
    float* keC = qeC + 64*ENC_STRIDE;         // [64][72]
    float* msm = keC + 64*ENC_STRIDE;         // [64]
    float* lsm = msm + 64;
    float* cf  = lsm + 64;
    unsigned* qb = (unsigned*)(cf + 64);      // [64]
    unsigned* kb = qb + 64;                   // [64]

    const int n0   = blockIdx.x * 64;
    const int b    = blockIdx.y;
    const int head = blockIdx.z;
    const int tid  = threadIdx.x;
    const int lane = tid & 31;
    const int w    = tid >> 5;                // 0..15
    const int wm = w >> 2, wn = w & 3;        // PV: 4 row-groups x 4 col-groups
    const int qr = lane >> 2, qc = lane & 3;

    float inv_sp = 1.f;
    if (head == 1) inv_sp = 1.f / log1pf(expf(t_temp[0]));
    float fw0 = 0.f, fw1 = 0.f, fw2 = 0.f;
    if (head == 3) {
        float p0 = p_fusion[0], p1 = p_fusion[1], p2 = p_fusion[2];
        float mx = fmaxf(p0, fmaxf(p1, p2));
        float e0 = expf(p0-mx), e1 = expf(p1-mx), e2 = expf(p2-mx);
        float inv = 1.f/(e0+e1+e2);
        fw0 = e0*inv; fw1 = e1*inv; fw2 = e2*inv;
    }

    if (tid < 64) { msm[tid] = -INFINITY; lsm[tid] = 0.f; }

    // ---- query encodings -> qeC (interleaved pairs), once ----
    if (head == 0) {
        if (tid < 64) qb[tid] = g_qbits[(b*SEQ + n0 + tid)*2 + 0];
    } else if (head == 3) {
        if (tid < 64) qb[tid] = g_qbits[(b*SEQ + n0 + tid)*2 + 1];
        for (int j = tid; j < 2048; j += 512) {
            int t = j >> 5, m = j & 31;
            const float* base = &g_qproj[(size_t)(b*SEQ + n0 + t)*PROJ];
            int slot = t*ENC_STRIDE + (m >> 1)*4 + (m & 1);
            qeC[slot]     = base[128+m];
            qeC[slot + 2] = base[160+m];
        }
    } else {
        int off = (head == 1) ? 32 : 64;
        for (int j = tid; j < 2048; j += 512) {
            int t = j >> 5, m = j & 31;
            qeC[t*ENC_STRIDE + (m >> 1)*4 + (m & 1)] =
                g_qproj[(size_t)(b*SEQ + n0 + t)*PROJ + off + m];
        }
    }

    // PV accumulators: warp = 16 rows x 64 cols (8 n-tiles of 8)
    float acc[8][4];
    #pragma unroll
    for (int i = 0; i < 8; ++i)
        #pragma unroll
        for (int j = 0; j < 4; ++j) acc[i][j] = 0.f;

    const float* vp_g = &g_Vp[(size_t)(b*SEQ)*1024 + head*HDIM];
    const int kk  = tid & 63;                 // score-phase key
    const int qb8 = tid >> 6;                 // score-phase query octet

    for (int k0i = 0; k0i < SEQ; k0i += 64) {
        __syncthreads();   // prior-tile consumers done / initial fills done

        // ---- stage Vp tile [64][256] -> tf32, stride 264 ----
        #pragma unroll
        for (int i = 0; i < 8; ++i) {
            int idx = tid + 512*i;
            int row = idx >> 6, c4 = idx & 63;
            float4 v = *(const float4*)&vp_g[(size_t)(k0i+row)*1024 + c4*4];
            unsigned* dst = (unsigned*)&vp[row*VP_STRIDE + c4*4];
            dst[0] = f2tf32(v.x); dst[1] = f2tf32(v.y);
            dst[2] = f2tf32(v.z); dst[3] = f2tf32(v.w);
        }
        // ---- key encodings -> keC ----
        if (head == 0) {
            if (tid < 64) kb[tid] = g_kbits[(b*SEQ + k0i + tid)*2 + 0];
        } else if (head == 3) {
            if (tid < 64) kb[tid] = g_kbits[(b*SEQ + k0i + tid)*2 + 1];
            for (int j = tid; j < 2048; j += 512) {
                int t = j >> 5, m = j & 31;
                const float* base = &g_kproj[(size_t)(b*SEQ + k0i + t)*PROJ];
                int slot = t*ENC_STRIDE + (m >> 1)*4 + (m & 1);
                keC[slot]     = base[128+m];
                keC[slot + 2] = base[160+m];
            }
        } else {
            int off = (head == 1) ? 32 : 64;
            for (int j = tid; j < 2048; j += 512) {
                int t = j >> 5, m = j & 31;
                keC[t*ENC_STRIDE + (m >> 1)*4 + (m & 1)] =
                    g_kproj[(size_t)(b*SEQ + k0i + t)*PROJ + off + m];
            }
        }
        __syncthreads();

        // ---- scores: thread = key kk x 8 queries (qb8*8+i) ----
        const int qbase = qb8*8;
        if (head == 0) {
            unsigned kr = kb[kk];
            #pragma unroll
            for (int i = 0; i < 8; ++i) {
                int p = __popc(qb[qbase+i] ^ kr);
                sc[(qbase+i)*SC_STRIDE + kk] = (1.f - p*(1.f/32.f)) * SCALEF;
            }
        } else if (head == 1) {
            float mna[8], mnb[8];
            #pragma unroll
            for (int i = 0; i < 8; ++i) { mna[i] = INFINITY; mnb[i] = INFINITY; }
            const ull* keu = (const ull*)&keC[kk*ENC_STRIDE];
            #pragma unroll
            for (int m2 = 0; m2 < 16; ++m2) {
                ull kv = keu[m2*2];
                #pragma unroll
                for (int i = 0; i < 8; ++i) {
                    ull qv = *(const ull*)&qeC[(qbase+i)*ENC_STRIDE + m2*4];
                    ull s = fadd2(qv, kv);
                    mna[i] = fminf(mna[i], ulo(s));
                    mnb[i] = fminf(mnb[i], uhi(s));
                }
            }
            #pragma unroll
            for (int i = 0; i < 8; ++i)
                sc[(qbase+i)*SC_STRIDE + kk] = -fminf(mna[i], mnb[i]) * inv_sp;
        } else if (head == 2) {
            ull dr[8];
            #pragma unroll
            for (int i = 0; i < 8; ++i) dr[i] = 0ull;
            const ull* keu = (const ull*)&keC[kk*ENC_STRIDE];
            #pragma unroll
            for (int m2 = 0; m2 < 16; ++m2) {
                ull kv = keu[m2*2];
                #pragma unroll
                for (int i = 0; i < 8; ++i) {
                    ull qv = *(const ull*)&qeC[(qbase+i)*ENC_STRIDE + m2*4];
                    dr[i] = ffma2(qv, kv, dr[i]);
                }
            }
            #pragma unroll
            for (int i = 0; i < 8; ++i)
                sc[(qbase+i)*SC_STRIDE + kk] = (ulo(dr[i]) + uhi(dr[i])) * SCALEF;
        } else {
            float mna[8], mnb[8];
            ull dr[8];
            #pragma unroll
            for (int i = 0; i < 8; ++i) { mna[i] = INFINITY; mnb[i] = INFINITY; dr[i] = 0ull; }
            const ulonglong2* keu = (const ulonglong2*)&keC[kk*ENC_STRIDE];
            #pragma unroll
            for (int m2 = 0; m2 < 16; ++m2) {
                ulonglong2 kv = keu[m2];
                #pragma unroll
                for (int i = 0; i < 8; ++i) {
                    ulonglong2 qv = *(const ulonglong2*)&qeC[(qbase+i)*ENC_STRIDE + m2*4];
                    ull s = fadd2(qv.x, kv.x);
                    mna[i] = fminf(mna[i], ulo(s));
                    mnb[i] = fminf(mnb[i], uhi(s));
                    dr[i] = ffma2(qv.y, kv.y, dr[i]);
                }
            }
            unsigned kr = kb[kk];
            #pragma unroll
            for (int i = 0; i < 8; ++i) {
                float simb = 1.f - __popc(qb[qbase+i] ^ kr)*(1.f/32.f);
                float s = fw0*simb - fw1*fminf(mna[i], mnb[i])
                        + fw2*(ulo(dr[i]) + uhi(dr[i]));
                sc[(qbase+i)*SC_STRIDE + kk] = s * SCALEF;
            }
        }
        __syncthreads();

        // ---- online softmax: warp w owns rows w*4..w*4+3; write P as tf32 ----
        #pragma unroll
        for (int j = 0; j < 4; ++j) {
            int q = w*4 + j;
            float s0 = sc[q*SC_STRIDE + lane], s1 = sc[q*SC_STRIDE + lane + 32];
            float tm = wredmax(fmaxf(s0, s1));
            float mold = msm[q];
            float mnew = fmaxf(mold, tm);
            float c  = __expf(mold - mnew);
            float p0 = __expf(s0 - mnew), p1 = __expf(s1 - mnew);
            sc[q*SC_STRIDE + lane]      = __uint_as_float(f2tf32(p0));
            sc[q*SC_STRIDE + lane + 32] = __uint_as_float(f2tf32(p1));
            float ls = wredsum(p0 + p1);
            if (lane == 0) { msm[q] = mnew; lsm[q] = lsm[q]*c + ls; cf[q] = c; }
        }
        __syncthreads();

        // ---- PV via tf32 mma ----
        {
            float clo = cf[wm*16 + qr], chi = cf[wm*16 + qr + 8];
            #pragma unroll
            for (int nt = 0; nt < 8; ++nt) {
                acc[nt][0] *= clo; acc[nt][1] *= clo;
                acc[nt][2] *= chi; acc[nt][3] *= chi;
            }
            const unsigned* scu = (const unsigned*)sc;
            const unsigned* vpu = (const unsigned*)vp;
            const int rlo = (wm*16 + qr)*SC_STRIDE, rhi = rlo + 8*SC_STRIDE;
            #pragma unroll
            for (int ks = 0; ks < 8; ++ks) {
                const int k0 = ks*8;
                unsigned a0 = scu[rlo + k0 + qc];
                unsigned a1 = scu[rhi + k0 + qc];
                unsigned a2 = scu[rlo + k0 + qc + 4];
                unsigned a3 = scu[rhi + k0 + qc + 4];
                const unsigned* v0 = &vpu[(k0+qc)*VP_STRIDE   + wn*64 + qr];
                const unsigned* v1 = &vpu[(k0+qc+4)*VP_STRIDE + wn*64 + qr];
                #pragma unroll
                for (int nt = 0; nt < 8; ++nt)
                    mma_tf32(acc[nt], a0, a1, a2, a3, v0[nt*8], v1[nt*8]);
            }
        }
    }

    // ---- epilogue: normalize + write fragments ----
    {
        int rlo = wm*16 + qr, rhi = rlo + 8;
        float il_lo = 1.f / lsm[rlo], il_hi = 1.f / lsm[rhi];
        float* out_lo = &g_cat[(size_t)(b*SEQ + n0 + rlo)*1024 + head*HDIM + wn*64];
        float* out_hi = &g_cat[(size_t)(b*SEQ + n0 + rhi)*1024 + head*HDIM + wn*64];
        #pragma unroll
        for (int nt = 0; nt < 8; ++nt) {
            int c0 = nt*8 + 2*qc;
            float2 o0, o1;
            o0.x = acc[nt][0]*il_lo; o0.y = acc[nt][1]*il_lo;
            o1.x = acc[nt][2]*il_hi; o1.y = acc[nt][3]*il_hi;
            *(float2*)&out_lo[c0] = o0;
            *(float2*)&out_hi[c0] = o1;
        }
    }
}

// ---------------- host launch ----------------
extern "C" void kernel_launch(void* const* d_in, const int* in_sizes, int n_in,
                              void* d_out, int out_size)
{
    const float* Q        = (const float*)d_in[0];
    const float* K        = (const float*)d_in[1];
    const float* V        = (const float*)d_in[2];
    const float* bq_w     = (const float*)d_in[3];
    const float* bq_b     = (const float*)d_in[4];
    const float* bk_w     = (const float*)d_in[5];
    const float* bk_b     = (const float*)d_in[6];
    const float* b_v      = (const float*)d_in[7];
    const float* tq_w     = (const float*)d_in[8];
    const float* tq_b     = (const float*)d_in[9];
    const float* tk_w     = (const float*)d_in[10];
    const float* tk_b     = (const float*)d_in[11];
    const float* t_v      = (const float*)d_in[12];
    const float* t_temp   = (const float*)d_in[13];
    const float* rq_w     = (const float*)d_in[14];
    const float* rq_b     = (const float*)d_in[15];
    const float* rk_w     = (const float*)d_in[16];
    const float* rk_b     = (const float*)d_in[17];
    const float* r_v      = (const float*)d_in[18];
    const float* pq_w     = (const float*)d_in[19];
    const float* pq_b     = (const float*)d_in[20];
    const float* pk_w     = (const float*)d_in[21];
    const float* pk_b     = (const float*)d_in[22];
    const float* p_v      = (const float*)d_in[23];
    const float* p_fusion = (const float*)d_in[24];
    const float* out_w    = (const float*)d_in[25];
    const float* out_b    = (const float*)d_in[26];
    float* out = (float*)d_out;

    void *pWq, *pWk, *pBq, *pBk, *pWv, *pqp, *pkp, *pVp, *pcat;
    cudaGetSymbolAddress(&pWq,  g_Wq);
    cudaGetSymbolAddress(&pWk,  g_Wk);
    cudaGetSymbolAddress(&pBq,  g_Bq);
    cudaGetSymbolAddress(&pBk,  g_Bk);
    cudaGetSymbolAddress(&pWv,  g_Wv);
    cudaGetSymbolAddress(&pqp,  g_qproj);
    cudaGetSymbolAddress(&pkp,  g_kproj);
    cudaGetSymbolAddress(&pVp,  g_Vp);
    cudaGetSymbolAddress(&pcat, g_cat);

    pack_weights<<<256, 256>>>(bq_w, tq_w, rq_w, pq_w, bq_b, tq_b, rq_b, pq_b,
                               bk_w, tk_w, rk_w, pk_w, bk_b, tk_b, rk_b, pk_b,
                               b_v, t_v, r_v, p_v);

    // Q/K projections (exact fp32): [2048 x 192 x 1024], z selects Q/K
    gemm_db<64,4><<<dim3(2, 32, 2), 256>>>(
        Q, K, (const float*)pWq, (const float*)pWk,
        (const float*)pBq, (const float*)pBk,
        (float*)pqp, (float*)pkp, NTOK, PROJ, DIM);

    // V projection (tf32 tensor cores): [2048 x 1024 x 1024]
    gemm_tc<<<dim3(8, 16), 256>>>(V, (const float*)pWv, nullptr,
                                  (float*)pVp, NTOK, 4*HDIM, DIM);

    pack_bits<<<NTOK*32/256, 256>>>();

    cudaFuncSetAttribute(attn_kernel, cudaFuncAttributeMaxDynamicSharedMemorySize,
                         ATTN_SMEM_BYTES);
    attn_kernel<<<dim3(SEQ/64, BATCH, 4), 512, ATTN_SMEM_BYTES>>>(t_temp, p_fusion);

    // output projection (tf32 tensor cores): [2048 x 1024 x 1024]
    gemm_tc<<<dim3(8, 16), 256>>>((const float*)pcat, out_w, out_b,
                                  out, NTOK, DIM, DIM);
}

// round 6
// speedup vs baseline: 1.0330x; 1.0330x over previous
#include <cuda_runtime.h>
#include <cuda_fp16.h>
#include <math.h>

// ---------------- problem constants ----------------
#define BATCH 2
#define SEQ   1024
#define DIM   1024
#define HDIM  256
#define MBITS 32
#define NTOK  (BATCH*SEQ)     // 2048
#define PROJ  192             // 6 groups x 32
#define SCALEF 0.17677669529663687f  // 1/sqrt(32)

typedef unsigned long long ull;

// ---------------- device scratch (static, no allocs) ----------------
__device__ float    g_Wq[PROJ*DIM];
__device__ float    g_Wk[PROJ*DIM];
__device__ float    g_Bq[PROJ];
__device__ float    g_Bk[PROJ];
__device__ float    g_qproj[NTOK*PROJ];
__device__ float    g_kproj[NTOK*PROJ];
__device__ unsigned g_qbits[NTOK*2];
__device__ unsigned g_kbits[NTOK*2];
__device__ float    g_Vp[NTOK*4*HDIM];
__device__ float    g_cat[NTOK*4*HDIM];

// ---------------- pack Q/K projection weights only ----------------
__global__ void pack_weights(
    const float* __restrict__ bq_w, const float* __restrict__ tq_w,
    const float* __restrict__ rq_w, const float* __restrict__ pq_w,
    const float* __restrict__ bq_b, const float* __restrict__ tq_b,
    const float* __restrict__ rq_b, const float* __restrict__ pq_b,
    const float* __restrict__ bk_w, const float* __restrict__ tk_w,
    const float* __restrict__ rk_w, const float* __restrict__ pk_w,
    const float* __restrict__ bk_b, const float* __restrict__ tk_b,
    const float* __restrict__ rk_b, const float* __restrict__ pk_b)
{
    int i0 = blockIdx.x * blockDim.x + threadIdx.x;
    int stride = gridDim.x * blockDim.x;
    for (int e = i0; e < PROJ*DIM; e += stride) {
        int r = e >> 10, d = e & 1023;
        int g = r >> 5, j = r & 31;
        const float* sq; const float* sk;
        switch (g) {
            case 0: sq = bq_w; sk = bk_w; break;
            case 1: sq = tq_w; sk = tk_w; break;
            case 2: sq = rq_w; sk = rk_w; break;
            default: sq = pq_w + (g-3)*MBITS*DIM; sk = pk_w + (g-3)*MBITS*DIM; break;
        }
        int off = j*DIM + d;
        g_Wq[e] = sq[off];
        g_Wk[e] = sk[off];
    }
    for (int e = i0; e < PROJ; e += stride) {
        int g = e >> 5, j = e & 31;
        float vq, vk;
        switch (g) {
            case 0: vq = bq_b[j]; vk = bk_b[j]; break;
            case 1: vq = tq_b[j]; vk = tk_b[j]; break;
            case 2: vq = rq_b[j]; vk = rk_b[j]; break;
            default: vq = pq_b[(g-3)*MBITS + j]; vk = pk_b[(g-3)*MBITS + j]; break;
        }
        g_Bq[e] = vq;
        g_Bk[e] = vk;
    }
}

// ---------------- fp32 double-buffered GEMM (exact QK projections) ----------
template<int BM, int TM>
__global__ __launch_bounds__(256) void gemm_db(
    const float* __restrict__ A0, const float* __restrict__ A1,
    const float* __restrict__ W0, const float* __restrict__ W1,
    const float* __restrict__ b0, const float* __restrict__ b1,
    float* __restrict__ C0, float* __restrict__ C1,
    int M, int N, int K)
{
    __shared__ __align__(16) float As[2][8][BM+4];
    __shared__ __align__(16) float Ws[2][8][132];

    const float* A    = blockIdx.z ? A1 : A0;
    const float* W    = blockIdx.z ? W1 : W0;
    const float* bias = blockIdx.z ? b1 : b0;
    float*       C    = blockIdx.z ? C1 : C0;

    const int bm = blockIdx.y * BM, bn = blockIdx.x * 128;
    const int tid = threadIdx.x;
    const int tx = tid & 15, ty = tid >> 4;
    const int lrow = tid >> 1, lc4 = (tid & 1) * 4;

    const bool aact = (tid < BM*2);
    const bool wact = (bn + lrow) < N;
    const float* Aptr = A + (size_t)(bm + lrow)*K + lc4;
    const float* Wptr = W + (size_t)(bn + lrow)*K + lc4;

    float acc[TM][8];
    #pragma unroll
    for (int i = 0; i < TM; ++i)
        #pragma unroll
        for (int j = 0; j < 8; ++j) acc[i][j] = 0.f;

    const int nt = K >> 3;
    float4 areg = make_float4(0,0,0,0), wreg = make_float4(0,0,0,0);
    if (aact) areg = *(const float4*)Aptr;
    if (wact) wreg = *(const float4*)Wptr;
    #pragma unroll
    for (int j = 0; j < 4; ++j) {
        if (aact) As[0][lc4+j][lrow] = (&areg.x)[j];
        Ws[0][lc4+j][lrow] = (&wreg.x)[j];
    }
    __syncthreads();

    for (int t = 0; t < nt; ++t) {
        const int cur = t & 1;
        if (t + 1 < nt) {
            if (aact) areg = *(const float4*)(Aptr + (t+1)*8);
            if (wact) wreg = *(const float4*)(Wptr + (t+1)*8);
        }
        #pragma unroll
        for (int kk = 0; kk < 8; ++kk) {
            float a[TM], b[8];
            *(float4*)&b[0] = *(const float4*)&Ws[cur][kk][tx*8];
            *(float4*)&b[4] = *(const float4*)&Ws[cur][kk][tx*8+4];
            *(float4*)&a[0] = *(const float4*)&As[cur][kk][ty*TM];
            if (TM == 8) *(float4*)&a[4] = *(const float4*)&As[cur][kk][ty*TM+4];
            #pragma unroll
            for (int i = 0; i < TM; ++i)
                #pragma unroll
                for (int j = 0; j < 8; ++j)
                    acc[i][j] += a[i]*b[j];
        }
        if (t + 1 < nt) {
            const int nxt = cur ^ 1;
            #pragma unroll
            for (int j = 0; j < 4; ++j) {
                if (aact) As[nxt][lc4+j][lrow] = (&areg.x)[j];
                Ws[nxt][lc4+j][lrow] = (&wreg.x)[j];
            }
        }
        __syncthreads();
    }

    #pragma unroll
    for (int i = 0; i < TM; ++i) {
        int row = bm + ty*TM + i;
        #pragma unroll
        for (int j4 = 0; j4 < 2; ++j4) {
            int col = bn + tx*8 + j4*4;
            if (col < N) {
                float4 o;
                o.x = acc[i][j4*4+0]; o.y = acc[i][j4*4+1];
                o.z = acc[i][j4*4+2]; o.w = acc[i][j4*4+3];
                if (bias) { o.x += bias[col]; o.y += bias[col+1]; o.z += bias[col+2]; o.w += bias[col+3]; }
                *(float4*)&C[(size_t)row*N + col] = o;
            }
        }
    }
}

// ---------------- tf32 helpers ----------------
__device__ __forceinline__ unsigned f2tf32(float f) {
    unsigned u;
    asm("cvt.rna.tf32.f32 %0, %1;" : "=r"(u) : "f"(f));
    return u;
}
__device__ __forceinline__ void mma_tf32(float c[4],
    unsigned a0, unsigned a1, unsigned a2, unsigned a3,
    unsigned b0, unsigned b1)
{
    asm("mma.sync.aligned.m16n8k8.row.col.f32.tf32.tf32.f32 "
        "{%0,%1,%2,%3},{%4,%5,%6,%7},{%8,%9},{%0,%1,%2,%3};"
        : "+f"(c[0]), "+f"(c[1]), "+f"(c[2]), "+f"(c[3])
        : "r"(a0), "r"(a1), "r"(a2), "r"(a3), "r"(b0), "r"(b1));
}

// ---------------- tf32 tensor-core GEMM body (shared by out-proj/V-proj) ----
__device__ __forceinline__ void gemm_tc_body(
    const float* __restrict__ A, const float* __restrict__ W,
    const float* __restrict__ bias, float* __restrict__ C,
    int M, int N, int K, int ldc, int bm, int bn)
{
    __shared__ unsigned As[2][8][136];
    __shared__ unsigned Ws[2][8][136];

    const int tid = threadIdx.x;
    const int w = tid >> 5, lane = tid & 31;
    const int wm = w >> 2, wn = w & 3;
    const int qr = lane >> 2, qc = lane & 3;
    const int lrow = tid >> 1, lc4 = (tid & 1) * 4;

    const float* Aptr = A + (size_t)(bm + lrow)*K + lc4;
    const float* Wptr = W + (size_t)(bn + lrow)*K + lc4;

    float acc[4][4][4];
    #pragma unroll
    for (int i = 0; i < 4; ++i)
        #pragma unroll
        for (int j = 0; j < 4; ++j)
            #pragma unroll
            for (int r = 0; r < 4; ++r) acc[i][j][r] = 0.f;

    const int nt = K >> 3;
    float4 areg = *(const float4*)Aptr;
    float4 wreg = *(const float4*)Wptr;
    #pragma unroll
    for (int j = 0; j < 4; ++j) {
        As[0][lc4+j][lrow] = f2tf32((&areg.x)[j]);
        Ws[0][lc4+j][lrow] = f2tf32((&wreg.x)[j]);
    }
    __syncthreads();

    for (int t = 0; t < nt; ++t) {
        const int cur = t & 1;
        if (t + 1 < nt) {
            areg = *(const float4*)(Aptr + (t+1)*8);
            wreg = *(const float4*)(Wptr + (t+1)*8);
        }
        unsigned af[4][4], bf[4][2];
        #pragma unroll
        for (int i = 0; i < 4; ++i) {
            int m0 = wm*64 + i*16 + qr;
            af[i][0] = As[cur][qc  ][m0];
            af[i][1] = As[cur][qc  ][m0+8];
            af[i][2] = As[cur][qc+4][m0];
            af[i][3] = As[cur][qc+4][m0+8];
        }
        #pragma unroll
        for (int j = 0; j < 4; ++j) {
            int n0 = wn*32 + j*8 + qr;
            bf[j][0] = Ws[cur][qc  ][n0];
            bf[j][1] = Ws[cur][qc+4][n0];
        }
        #pragma unroll
        for (int i = 0; i < 4; ++i)
            #pragma unroll
            for (int j = 0; j < 4; ++j)
                mma_tf32(acc[i][j], af[i][0], af[i][1], af[i][2], af[i][3],
                         bf[j][0], bf[j][1]);
        if (t + 1 < nt) {
            const int nxt = cur ^ 1;
            #pragma unroll
            for (int j = 0; j < 4; ++j) {
                As[nxt][lc4+j][lrow] = f2tf32((&areg.x)[j]);
                Ws[nxt][lc4+j][lrow] = f2tf32((&wreg.x)[j]);
            }
        }
        __syncthreads();
    }

    #pragma unroll
    for (int i = 0; i < 4; ++i) {
        int r0 = bm + wm*64 + i*16 + qr;
        #pragma unroll
        for (int j = 0; j < 4; ++j) {
            int c0 = bn + wn*32 + j*8 + 2*qc;
            float bx = 0.f, by = 0.f;
            if (bias) { bx = bias[c0]; by = bias[c0+1]; }
            float2 o0, o1;
            o0.x = acc[i][j][0] + bx; o0.y = acc[i][j][1] + by;
            o1.x = acc[i][j][2] + bx; o1.y = acc[i][j][3] + by;
            *(float2*)&C[(size_t)r0*ldc + c0]     = o0;
            *(float2*)&C[(size_t)(r0+8)*ldc + c0] = o1;
        }
    }
}

__global__ __launch_bounds__(256) void gemm_tc(
    const float* __restrict__ A, const float* __restrict__ W,
    const float* __restrict__ bias, float* __restrict__ C,
    int M, int N, int K)
{
    gemm_tc_body(A, W, bias, C, M, N, K, N, blockIdx.y*128, blockIdx.x*128);
}

// V projection per head: z selects the head's value weight, C strided (ldc=1024)
__global__ __launch_bounds__(256) void gemm_tcv(
    const float* __restrict__ V,
    const float* __restrict__ w0, const float* __restrict__ w1,
    const float* __restrict__ w2, const float* __restrict__ w3,
    float* __restrict__ C)
{
    const float* W = (blockIdx.z == 0) ? w0 : (blockIdx.z == 1) ? w1
                   : (blockIdx.z == 2) ? w2 : w3;
    gemm_tc_body(V, W, nullptr, C + blockIdx.z*HDIM,
                 NTOK, HDIM, DIM, 4*HDIM, blockIdx.y*128, blockIdx.x*128);
}

// ---------------- bit packing for boolean heads ----------------
__global__ void pack_bits()
{
    int gw = (blockIdx.x * blockDim.x + threadIdx.x) >> 5;
    int lane = threadIdx.x & 31;
    if (gw >= NTOK) return;
    unsigned q0 = __ballot_sync(0xffffffffu, g_qproj[(size_t)gw*PROJ + lane]       > 0.f);
    unsigned q1 = __ballot_sync(0xffffffffu, g_qproj[(size_t)gw*PROJ + 96 + lane]  > 0.f);
    unsigned k0 = __ballot_sync(0xffffffffu, g_kproj[(size_t)gw*PROJ + lane]       > 0.f);
    unsigned k1 = __ballot_sync(0xffffffffu, g_kproj[(size_t)gw*PROJ + 96 + lane]  > 0.f);
    if (lane == 0) {
        g_qbits[gw*2]   = q0; g_qbits[gw*2+1] = q1;
        g_kbits[gw*2]   = k0; g_kbits[gw*2+1] = k1;
    }
}

// ---------------- fused attention: 64 q x 1 head per block, 256 threads ----
__device__ __forceinline__ float wredmax(float v) {
    #pragma unroll
    for (int o = 16; o; o >>= 1) v = fmaxf(v, __shfl_xor_sync(0xffffffffu, v, o));
    return v;
}
__device__ __forceinline__ float wredsum(float v) {
    #pragma unroll
    for (int o = 16; o; o >>= 1) v += __shfl_xor_sync(0xffffffffu, v, o);
    return v;
}

#define VP_STRIDE 264
#define SC_STRIDE 68
#define RE_STRIDE 34     // fp32 real-encoding row stride (LDS.64 conflict-free)
#define TR_STRIDE 17     // half2 tropical-encoding row stride (conflict-free)
// floats: vp 64*264 | sc 64*68 | qer,ker 64*34 each | qet,ket 64*17 each (half2=1 float)
//         | msm,lsm,cf 192 | qb,kb 128
#define ATTN_SMEM_FLOATS (64*VP_STRIDE + 64*SC_STRIDE + 2*64*RE_STRIDE + 2*64*TR_STRIDE + 192 + 128)
#define ATTN_SMEM_BYTES  (ATTN_SMEM_FLOATS*4)

__global__ __launch_bounds__(256) void attn_kernel(const float* __restrict__ t_temp,
                                                   const float* __restrict__ p_fusion)
{
    extern __shared__ __align__(16) float sm[];
    float*   vp  = sm;                        // [64][264] tf32 bits
    float*   sc  = vp + 64*VP_STRIDE;         // [64][68]
    float*   qer = sc + 64*SC_STRIDE;         // [64][34] real fp32
    float*   ker = qer + 64*RE_STRIDE;        // [64][34]
    __half2* qet = (__half2*)(ker + 64*RE_STRIDE);  // [64][17]
    __half2* ket = qet + 64*TR_STRIDE;              // [64][17]
    float*   msm = (float*)(ket + 64*TR_STRIDE);    // [64]
    float*   lsm = msm + 64;
    float*   cf  = lsm + 64;
    unsigned* qb = (unsigned*)(cf + 64);      // [64]
    unsigned* kb = qb + 64;                   // [64]

    const int n0   = blockIdx.x * 64;
    const int b    = blockIdx.y;
    const int head = blockIdx.z;
    const int tid  = threadIdx.x;
    const int lane = tid & 31;
    const int w    = tid >> 5;
    const int wm = w >> 1, wn = w & 1;        // PV: 4 row-groups x 2 col-halves
    const int qr = lane >> 2, qc = lane & 3;

    float inv_sp = 1.f;
    if (head == 1) inv_sp = 1.f / log1pf(expf(t_temp[0]));
    float fw0 = 0.f, fw1 = 0.f, fw2 = 0.f;
    if (head == 3) {
        float p0 = p_fusion[0], p1 = p_fusion[1], p2 = p_fusion[2];
        float mx = fmaxf(p0, fmaxf(p1, p2));
        float e0 = expf(p0-mx), e1 = expf(p1-mx), e2 = expf(p2-mx);
        float inv = 1.f/(e0+e1+e2);
        fw0 = e0*inv; fw1 = e1*inv; fw2 = e2*inv;
    }

    if (tid < 64) { msm[tid] = -INFINITY; lsm[tid] = 0.f; }

    // ---- query encodings (once) ----
    if (head == 0) {
        if (tid < 64) qb[tid] = g_qbits[(b*SEQ + n0 + tid)*2 + 0];
    } else if (head == 1) {
        for (int j = tid; j < 1024; j += 256) {
            int t = j >> 4, m = j & 15;
            const float* base = &g_qproj[(size_t)(b*SEQ + n0 + t)*PROJ];
            qet[t*TR_STRIDE + m] = __floats2half2_rn(base[32+2*m], base[33+2*m]);
        }
    } else if (head == 2) {
        for (int j = tid; j < 2048; j += 256) {
            int t = j >> 5, m = j & 31;
            qer[t*RE_STRIDE + m] = g_qproj[(size_t)(b*SEQ + n0 + t)*PROJ + 64 + m];
        }
    } else {
        if (tid < 64) qb[tid] = g_qbits[(b*SEQ + n0 + tid)*2 + 1];
        for (int j = tid; j < 1024; j += 256) {
            int t = j >> 4, m = j & 15;
            const float* base = &g_qproj[(size_t)(b*SEQ + n0 + t)*PROJ];
            qet[t*TR_STRIDE + m] = __floats2half2_rn(base[128+2*m], base[129+2*m]);
        }
        for (int j = tid; j < 2048; j += 256) {
            int t = j >> 5, m = j & 31;
            qer[t*RE_STRIDE + m] = g_qproj[(size_t)(b*SEQ + n0 + t)*PROJ + 160 + m];
        }
    }

    // PV mma accumulators: warp = 16 rows x 128 cols, 16 n-tiles of 8
    float acc[16][4];
    #pragma unroll
    for (int i = 0; i < 16; ++i)
        #pragma unroll
        for (int j = 0; j < 4; ++j) acc[i][j] = 0.f;

    const float* vp_g = &g_Vp[(size_t)(b*SEQ)*1024 + head*HDIM];
    const int kk  = tid & 63;
    const int qb4 = tid >> 6;

    for (int k0i = 0; k0i < SEQ; k0i += 64) {
        __syncthreads();

        // ---- stage Vp tile [64][256] -> tf32 ----
        #pragma unroll
        for (int i = 0; i < 16; ++i) {
            int idx = tid + 256*i;
            int row = idx >> 6, c4 = idx & 63;
            float4 v = *(const float4*)&vp_g[(size_t)(k0i+row)*1024 + c4*4];
            unsigned* dst = (unsigned*)&vp[row*VP_STRIDE + c4*4];
            dst[0] = f2tf32(v.x); dst[1] = f2tf32(v.y);
            dst[2] = f2tf32(v.z); dst[3] = f2tf32(v.w);
        }
        // ---- key encodings ----
        if (head == 0) {
            if (tid < 64) kb[tid] = g_kbits[(b*SEQ + k0i + tid)*2 + 0];
        } else if (head == 1) {
            for (int j = tid; j < 1024; j += 256) {
                int t = j >> 4, m = j & 15;
                const float* base = &g_kproj[(size_t)(b*SEQ + k0i + t)*PROJ];
                ket[t*TR_STRIDE + m] = __floats2half2_rn(base[32+2*m], base[33+2*m]);
            }
        } else if (head == 2) {
            for (int j = tid; j < 2048; j += 256) {
                int t = j >> 5, m = j & 31;
                ker[t*RE_STRIDE + m] = g_kproj[(size_t)(b*SEQ + k0i + t)*PROJ + 64 + m];
            }
        } else {
            if (tid < 64) kb[tid] = g_kbits[(b*SEQ + k0i + tid)*2 + 1];
            for (int j = tid; j < 1024; j += 256) {
                int t = j >> 4, m = j & 15;
                const float* base = &g_kproj[(size_t)(b*SEQ + k0i + t)*PROJ];
                ket[t*TR_STRIDE + m] = __floats2half2_rn(base[128+2*m], base[129+2*m]);
            }
            for (int j = tid; j < 2048; j += 256) {
                int t = j >> 5, m = j & 31;
                ker[t*RE_STRIDE + m] = g_kproj[(size_t)(b*SEQ + k0i + t)*PROJ + 160 + m];
            }
        }
        __syncthreads();

        // ---- scores: thread = key kk x 16 queries ----
        const int qbase = qb4*16;
        if (head == 0) {
            unsigned kr = kb[kk];
            #pragma unroll
            for (int i = 0; i < 16; ++i) {
                int p = __popc(qb[qbase+i] ^ kr);
                sc[(qbase+i)*SC_STRIDE + kk] = (1.f - p*(1.f/32.f)) * SCALEF;
            }
        } else if (head == 1) {
            __half2 kr[16];
            const __half2* krow = &ket[kk*TR_STRIDE];
            #pragma unroll
            for (int m = 0; m < 16; ++m) kr[m] = krow[m];
            #pragma unroll 4
            for (int i = 0; i < 16; ++i) {
                const __half2* qe = &qet[(qbase+i)*TR_STRIDE];
                __half2 mnA = __hadd2(qe[0], kr[0]);
                __half2 mnB = __hadd2(qe[1], kr[1]);
                #pragma unroll
                for (int m = 2; m < 16; m += 2) {
                    mnA = __hmin2(mnA, __hadd2(qe[m],   kr[m]));
                    mnB = __hmin2(mnB, __hadd2(qe[m+1], kr[m+1]));
                }
                __half2 mn = __hmin2(mnA, mnB);
                float mnf = fminf(__low2float(mn), __high2float(mn));
                sc[(qbase+i)*SC_STRIDE + kk] = -mnf * inv_sp;
            }
        } else if (head == 2) {
            float krr[32];
            const float* krow = &ker[kk*RE_STRIDE];
            #pragma unroll
            for (int m = 0; m < 32; ++m) krr[m] = krow[m];
            #pragma unroll 4
            for (int i = 0; i < 16; ++i) {
                const float* qe = &qer[(qbase+i)*RE_STRIDE];
                float da = 0.f, db = 0.f;
                #pragma unroll
                for (int m = 0; m < 32; m += 2) {
                    da = fmaf(qe[m],   krr[m],   da);
                    db = fmaf(qe[m+1], krr[m+1], db);
                }
                sc[(qbase+i)*SC_STRIDE + kk] = (da + db) * SCALEF;
            }
        } else {
            __half2 krt[16];
            float krr[32];
            const __half2* ktrow = &ket[kk*TR_STRIDE];
            const float* krrow = &ker[kk*RE_STRIDE];
            #pragma unroll
            for (int m = 0; m < 16; ++m) krt[m] = ktrow[m];
            #pragma unroll
            for (int m = 0; m < 32; ++m) krr[m] = krrow[m];
            unsigned kr = kb[kk];
            #pragma unroll 2
            for (int i = 0; i < 16; ++i) {
                const __half2* qe = &qet[(qbase+i)*TR_STRIDE];
                const float* qf  = &qer[(qbase+i)*RE_STRIDE];
                __half2 mnA = __hadd2(qe[0], krt[0]);
                __half2 mnB = __hadd2(qe[1], krt[1]);
                float da = 0.f, db = 0.f;
                #pragma unroll
                for (int m = 2; m < 16; m += 2) {
                    mnA = __hmin2(mnA, __hadd2(qe[m],   krt[m]));
                    mnB = __hmin2(mnB, __hadd2(qe[m+1], krt[m+1]));
                }
                #pragma unroll
                for (int m = 0; m < 32; m += 2) {
                    da = fmaf(qf[m],   krr[m],   da);
                    db = fmaf(qf[m+1], krr[m+1], db);
                }
                __half2 mn = __hmin2(mnA, mnB);
                float mnf = fminf(__low2float(mn), __high2float(mn));
                float simb = 1.f - __popc(qb[qbase+i] ^ kr)*(1.f/32.f);
                float s = fw0*simb - fw1*mnf + fw2*(da + db);
                sc[(qbase+i)*SC_STRIDE + kk] = s * SCALEF;
            }
        }
        __syncthreads();

        // ---- online softmax: warp w owns rows w*8..w*8+7; write P as tf32 ----
        #pragma unroll
        for (int j = 0; j < 8; ++j) {
            int q = w*8 + j;
            float s0 = sc[q*SC_STRIDE + lane], s1 = sc[q*SC_STRIDE + lane + 32];
            float tm = wredmax(fmaxf(s0, s1));
            float mold = msm[q];
            float mnew = fmaxf(mold, tm);
            float c  = __expf(mold - mnew);
            float p0 = __expf(s0 - mnew), p1 = __expf(s1 - mnew);
            sc[q*SC_STRIDE + lane]      = __uint_as_float(f2tf32(p0));
            sc[q*SC_STRIDE + lane + 32] = __uint_as_float(f2tf32(p1));
            float ls = wredsum(p0 + p1);
            if (lane == 0) { msm[q] = mnew; lsm[q] = lsm[q]*c + ls; cf[q] = c; }
        }
        __syncthreads();

        // ---- PV via tf32 mma: rescale fragments, 8 k-steps x 16 n-tiles ----
        {
            float clo = cf[wm*16 + qr], chi = cf[wm*16 + qr + 8];
            #pragma unroll
            for (int nt = 0; nt < 16; ++nt) {
                acc[nt][0] *= clo; acc[nt][1] *= clo;
                acc[nt][2] *= chi; acc[nt][3] *= chi;
            }
            const unsigned* scu = (const unsigned*)sc;
            const unsigned* vpu = (const unsigned*)vp;
            const int rlo = (wm*16 + qr)*SC_STRIDE, rhi = rlo + 8*SC_STRIDE;
            #pragma unroll
            for (int ks = 0; ks < 8; ++ks) {
                const int k0 = ks*8;
                unsigned a0 = scu[rlo + k0 + qc];
                unsigned a1 = scu[rhi + k0 + qc];
                unsigned a2 = scu[rlo + k0 + qc + 4];
                unsigned a3 = scu[rhi + k0 + qc + 4];
                const unsigned* v0 = &vpu[(k0+qc)*VP_STRIDE   + wn*128 + qr];
                const unsigned* v1 = &vpu[(k0+qc+4)*VP_STRIDE + wn*128 + qr];
                #pragma unroll
                for (int nt = 0; nt < 16; ++nt)
                    mma_tf32(acc[nt], a0, a1, a2, a3, v0[nt*8], v1[nt*8]);
            }
        }
    }

    // ---- epilogue: normalize + write fragments ----
    {
        int rlo = wm*16 + qr, rhi = rlo + 8;
        float il_lo = 1.f / lsm[rlo], il_hi = 1.f / lsm[rhi];
        float* out_lo = &g_cat[(size_t)(b*SEQ + n0 + rlo)*1024 + head*HDIM + wn*128];
        float* out_hi = &g_cat[(size_t)(b*SEQ + n0 + rhi)*1024 + head*HDIM + wn*128];
        #pragma unroll
        for (int nt = 0; nt < 16; ++nt) {
            int c0 = nt*8 + 2*qc;
            float2 o0, o1;
            o0.x = acc[nt][0]*il_lo; o0.y = acc[nt][1]*il_lo;
            o1.x = acc[nt][2]*il_hi; o1.y = acc[nt][3]*il_hi;
            *(float2*)&out_lo[c0] = o0;
            *(float2*)&out_hi[c0] = o1;
        }
    }
}

// ---------------- host launch ----------------
extern "C" void kernel_launch(void* const* d_in, const int* in_sizes, int n_in,
                              void* d_out, int out_size)
{
    const float* Q        = (const float*)d_in[0];
    const float* K        = (const float*)d_in[1];
    const float* V        = (const float*)d_in[2];
    const float* bq_w     = (const float*)d_in[3];
    const float* bq_b     = (const float*)d_in[4];
    const float* bk_w     = (const float*)d_in[5];
    const float* bk_b     = (const float*)d_in[6];
    const float* b_v      = (const float*)d_in[7];
    const float* tq_w     = (const float*)d_in[8];
    const float* tq_b     = (const float*)d_in[9];
    const float* tk_w     = (const float*)d_in[10];
    const float* tk_b     = (const float*)d_in[11];
    const float* t_v      = (const float*)d_in[12];
    const float* t_temp   = (const float*)d_in[13];
    const float* rq_w     = (const float*)d_in[14];
    const float* rq_b     = (const float*)d_in[15];
    const float* rk_w     = (const float*)d_in[16];
    const float* rk_b     = (const float*)d_in[17];
    const float* r_v      = (const float*)d_in[18];
    const float* pq_w     = (const float*)d_in[19];
    const float* pq_b     = (const float*)d_in[20];
    const float* pk_w     = (const float*)d_in[21];
    const float* pk_b     = (const float*)d_in[22];
    const float* p_v      = (const float*)d_in[23];
    const float* p_fusion = (const float*)d_in[24];
    const float* out_w    = (const float*)d_in[25];
    const float* out_b    = (const float*)d_in[26];
    float* out = (float*)d_out;

    void *pWq, *pWk, *pBq, *pBk, *pqp, *pkp, *pVp, *pcat;
    cudaGetSymbolAddress(&pWq,  g_Wq);
    cudaGetSymbolAddress(&pWk,  g_Wk);
    cudaGetSymbolAddress(&pBq,  g_Bq);
    cudaGetSymbolAddress(&pBk,  g_Bk);
    cudaGetSymbolAddress(&pqp,  g_qproj);
    cudaGetSymbolAddress(&pkp,  g_kproj);
    cudaGetSymbolAddress(&pVp,  g_Vp);
    cudaGetSymbolAddress(&pcat, g_cat);

    pack_weights<<<128, 256>>>(bq_w, tq_w, rq_w, pq_w, bq_b, tq_b, rq_b, pq_b,
                               bk_w, tk_w, rk_w, pk_w, bk_b, tk_b, rk_b, pk_b);

    // Q/K projections (exact fp32): [2048 x 192 x 1024], z selects Q/K
    gemm_db<64,4><<<dim3(2, 32, 2), 256>>>(
        Q, K, (const float*)pWq, (const float*)pWk,
        (const float*)pBq, (const float*)pBk,
        (float*)pqp, (float*)pkp, NTOK, PROJ, DIM);

    // V projection (tf32, per head via z; writes strided into g_Vp)
    gemm_tcv<<<dim3(2, 16, 4), 256>>>(V, b_v, t_v, r_v, p_v, (float*)pVp);

    pack_bits<<<NTOK*32/256, 256>>>();

    cudaFuncSetAttribute(attn_kernel, cudaFuncAttributeMaxDynamicSharedMemorySize,
                         ATTN_SMEM_BYTES);
    attn_kernel<<<dim3(SEQ/64, BATCH, 4), 256, ATTN_SMEM_BYTES>>>(t_temp, p_fusion);

    // output projection (tf32 tensor cores): [2048 x 1024 x 1024]
    gemm_tc<<<dim3(8, 16), 256>>>((const float*)pcat, out_w, out_b,
                                  out, NTOK, DIM, DIM);
}

// round 7
// speedup vs baseline: 1.0562x; 1.0224x over previous
#include <cuda_runtime.h>
#include <cuda_fp16.h>
#include <math.h>

// ---------------- problem constants ----------------
#define BATCH 2
#define SEQ   1024
#define DIM   1024
#define HDIM  256
#define MBITS 32
#define NTOK  (BATCH*SEQ)     // 2048
#define PROJ  192             // 6 groups x 32
#define SCALEF 0.17677669529663687f  // 1/sqrt(32)

// ---------------- device scratch (static, no allocs) ----------------
__device__ float    g_Wq[PROJ*DIM];
__device__ float    g_Wk[PROJ*DIM];
__device__ float    g_Bq[PROJ];
__device__ float    g_Bk[PROJ];
__device__ float    g_qproj[NTOK*PROJ];
__device__ float    g_kproj[NTOK*PROJ];
__device__ unsigned g_qbits[NTOK*2];
__device__ unsigned g_kbits[NTOK*2];
__device__ float    g_Vp[NTOK*4*HDIM];
__device__ float    g_cat[NTOK*4*HDIM];
__device__ float    g_S[8u*1024u*1024u];   // [b*4+head][q][k] scores, 32MB
__device__ float    g_m[8*1024];           // row max
__device__ float    g_il[8*1024];          // 1/row sumexp

// ---------------- pack Q/K projection weights only ----------------
__global__ void pack_weights(
    const float* __restrict__ bq_w, const float* __restrict__ tq_w,
    const float* __restrict__ rq_w, const float* __restrict__ pq_w,
    const float* __restrict__ bq_b, const float* __restrict__ tq_b,
    const float* __restrict__ rq_b, const float* __restrict__ pq_b,
    const float* __restrict__ bk_w, const float* __restrict__ tk_w,
    const float* __restrict__ rk_w, const float* __restrict__ pk_w,
    const float* __restrict__ bk_b, const float* __restrict__ tk_b,
    const float* __restrict__ rk_b, const float* __restrict__ pk_b)
{
    int i0 = blockIdx.x * blockDim.x + threadIdx.x;
    int stride = gridDim.x * blockDim.x;
    for (int e = i0; e < PROJ*DIM; e += stride) {
        int r = e >> 10, d = e & 1023;
        int g = r >> 5, j = r & 31;
        const float* sq; const float* sk;
        switch (g) {
            case 0: sq = bq_w; sk = bk_w; break;
            case 1: sq = tq_w; sk = tk_w; break;
            case 2: sq = rq_w; sk = rk_w; break;
            default: sq = pq_w + (g-3)*MBITS*DIM; sk = pk_w + (g-3)*MBITS*DIM; break;
        }
        int off = j*DIM + d;
        g_Wq[e] = sq[off];
        g_Wk[e] = sk[off];
    }
    for (int e = i0; e < PROJ; e += stride) {
        int g = e >> 5, j = e & 31;
        float vq, vk;
        switch (g) {
            case 0: vq = bq_b[j]; vk = bk_b[j]; break;
            case 1: vq = tq_b[j]; vk = tk_b[j]; break;
            case 2: vq = rq_b[j]; vk = rk_b[j]; break;
            default: vq = pq_b[(g-3)*MBITS + j]; vk = pk_b[(g-3)*MBITS + j]; break;
        }
        g_Bq[e] = vq;
        g_Bk[e] = vk;
    }
}

// ---------------- fp32 double-buffered GEMM (exact QK projections) ----------
template<int BM, int TM>
__global__ __launch_bounds__(256) void gemm_db(
    const float* __restrict__ A0, const float* __restrict__ A1,
    const float* __restrict__ W0, const float* __restrict__ W1,
    const float* __restrict__ b0, const float* __restrict__ b1,
    float* __restrict__ C0, float* __restrict__ C1,
    int M, int N, int K)
{
    __shared__ __align__(16) float As[2][8][BM+4];
    __shared__ __align__(16) float Ws[2][8][132];

    const float* A    = blockIdx.z ? A1 : A0;
    const float* W    = blockIdx.z ? W1 : W0;
    const float* bias = blockIdx.z ? b1 : b0;
    float*       C    = blockIdx.z ? C1 : C0;

    const int bm = blockIdx.y * BM, bn = blockIdx.x * 128;
    const int tid = threadIdx.x;
    const int tx = tid & 15, ty = tid >> 4;
    const int lrow = tid >> 1, lc4 = (tid & 1) * 4;

    const bool aact = (tid < BM*2);
    const bool wact = (bn + lrow) < N;
    const float* Aptr = A + (size_t)(bm + lrow)*K + lc4;
    const float* Wptr = W + (size_t)(bn + lrow)*K + lc4;

    float acc[TM][8];
    #pragma unroll
    for (int i = 0; i < TM; ++i)
        #pragma unroll
        for (int j = 0; j < 8; ++j) acc[i][j] = 0.f;

    const int nt = K >> 3;
    float4 areg = make_float4(0,0,0,0), wreg = make_float4(0,0,0,0);
    if (aact) areg = *(const float4*)Aptr;
    if (wact) wreg = *(const float4*)Wptr;
    #pragma unroll
    for (int j = 0; j < 4; ++j) {
        if (aact) As[0][lc4+j][lrow] = (&areg.x)[j];
        Ws[0][lc4+j][lrow] = (&wreg.x)[j];
    }
    __syncthreads();

    for (int t = 0; t < nt; ++t) {
        const int cur = t & 1;
        if (t + 1 < nt) {
            if (aact) areg = *(const float4*)(Aptr + (t+1)*8);
            if (wact) wreg = *(const float4*)(Wptr + (t+1)*8);
        }
        #pragma unroll
        for (int kk = 0; kk < 8; ++kk) {
            float a[TM], b[8];
            *(float4*)&b[0] = *(const float4*)&Ws[cur][kk][tx*8];
            *(float4*)&b[4] = *(const float4*)&Ws[cur][kk][tx*8+4];
            *(float4*)&a[0] = *(const float4*)&As[cur][kk][ty*TM];
            if (TM == 8) *(float4*)&a[4] = *(const float4*)&As[cur][kk][ty*TM+4];
            #pragma unroll
            for (int i = 0; i < TM; ++i)
                #pragma unroll
                for (int j = 0; j < 8; ++j)
                    acc[i][j] += a[i]*b[j];
        }
        if (t + 1 < nt) {
            const int nxt = cur ^ 1;
            #pragma unroll
            for (int j = 0; j < 4; ++j) {
                if (aact) As[nxt][lc4+j][lrow] = (&areg.x)[j];
                Ws[nxt][lc4+j][lrow] = (&wreg.x)[j];
            }
        }
        __syncthreads();
    }

    #pragma unroll
    for (int i = 0; i < TM; ++i) {
        int row = bm + ty*TM + i;
        #pragma unroll
        for (int j4 = 0; j4 < 2; ++j4) {
            int col = bn + tx*8 + j4*4;
            if (col < N) {
                float4 o;
                o.x = acc[i][j4*4+0]; o.y = acc[i][j4*4+1];
                o.z = acc[i][j4*4+2]; o.w = acc[i][j4*4+3];
                if (bias) { o.x += bias[col]; o.y += bias[col+1]; o.z += bias[col+2]; o.w += bias[col+3]; }
                *(float4*)&C[(size_t)row*N + col] = o;
            }
        }
    }
}

// ---------------- tf32 helpers ----------------
__device__ __forceinline__ unsigned f2tf32(float f) {
    unsigned u;
    asm("cvt.rna.tf32.f32 %0, %1;" : "=r"(u) : "f"(f));
    return u;
}
__device__ __forceinline__ void mma_tf32(float c[4],
    unsigned a0, unsigned a1, unsigned a2, unsigned a3,
    unsigned b0, unsigned b1)
{
    asm("mma.sync.aligned.m16n8k8.row.col.f32.tf32.tf32.f32 "
        "{%0,%1,%2,%3},{%4,%5,%6,%7},{%8,%9},{%0,%1,%2,%3};"
        : "+f"(c[0]), "+f"(c[1]), "+f"(c[2]), "+f"(c[3])
        : "r"(a0), "r"(a1), "r"(a2), "r"(a3), "r"(b0), "r"(b1));
}

// ---------------- tf32 tensor-core GEMM body (out-proj / V-proj) ----------
__device__ __forceinline__ void gemm_tc_body(
    const float* __restrict__ A, const float* __restrict__ W,
    const float* __restrict__ bias, float* __restrict__ C,
    int M, int N, int K, int ldc, int bm, int bn)
{
    __shared__ unsigned As[2][8][136];
    __shared__ unsigned Ws[2][8][136];

    const int tid = threadIdx.x;
    const int w = tid >> 5, lane = tid & 31;
    const int wm = w >> 2, wn = w & 3;
    const int qr = lane >> 2, qc = lane & 3;
    const int lrow = tid >> 1, lc4 = (tid & 1) * 4;

    const float* Aptr = A + (size_t)(bm + lrow)*K + lc4;
    const float* Wptr = W + (size_t)(bn + lrow)*K + lc4;

    float acc[4][4][4];
    #pragma unroll
    for (int i = 0; i < 4; ++i)
        #pragma unroll
        for (int j = 0; j < 4; ++j)
            #pragma unroll
            for (int r = 0; r < 4; ++r) acc[i][j][r] = 0.f;

    const int nt = K >> 3;
    float4 areg = *(const float4*)Aptr;
    float4 wreg = *(const float4*)Wptr;
    #pragma unroll
    for (int j = 0; j < 4; ++j) {
        As[0][lc4+j][lrow] = f2tf32((&areg.x)[j]);
        Ws[0][lc4+j][lrow] = f2tf32((&wreg.x)[j]);
    }
    __syncthreads();

    for (int t = 0; t < nt; ++t) {
        const int cur = t & 1;
        if (t + 1 < nt) {
            areg = *(const float4*)(Aptr + (t+1)*8);
            wreg = *(const float4*)(Wptr + (t+1)*8);
        }
        unsigned af[4][4], bf[4][2];
        #pragma unroll
        for (int i = 0; i < 4; ++i) {
            int m0 = wm*64 + i*16 + qr;
            af[i][0] = As[cur][qc  ][m0];
            af[i][1] = As[cur][qc  ][m0+8];
            af[i][2] = As[cur][qc+4][m0];
            af[i][3] = As[cur][qc+4][m0+8];
        }
        #pragma unroll
        for (int j = 0; j < 4; ++j) {
            int n0 = wn*32 + j*8 + qr;
            bf[j][0] = Ws[cur][qc  ][n0];
            bf[j][1] = Ws[cur][qc+4][n0];
        }
        #pragma unroll
        for (int i = 0; i < 4; ++i)
            #pragma unroll
            for (int j = 0; j < 4; ++j)
                mma_tf32(acc[i][j], af[i][0], af[i][1], af[i][2], af[i][3],
                         bf[j][0], bf[j][1]);
        if (t + 1 < nt) {
            const int nxt = cur ^ 1;
            #pragma unroll
            for (int j = 0; j < 4; ++j) {
                As[nxt][lc4+j][lrow] = f2tf32((&areg.x)[j]);
                Ws[nxt][lc4+j][lrow] = f2tf32((&wreg.x)[j]);
            }
        }
        __syncthreads();
    }

    #pragma unroll
    for (int i = 0; i < 4; ++i) {
        int r0 = bm + wm*64 + i*16 + qr;
        #pragma unroll
        for (int j = 0; j < 4; ++j) {
            int c0 = bn + wn*32 + j*8 + 2*qc;
            float bx = 0.f, by = 0.f;
            if (bias) { bx = bias[c0]; by = bias[c0+1]; }
            float2 o0, o1;
            o0.x = acc[i][j][0] + bx; o0.y = acc[i][j][1] + by;
            o1.x = acc[i][j][2] + bx; o1.y = acc[i][j][3] + by;
            *(float2*)&C[(size_t)r0*ldc + c0]     = o0;
            *(float2*)&C[(size_t)(r0+8)*ldc + c0] = o1;
        }
    }
}

__global__ __launch_bounds__(256) void gemm_tc(
    const float* __restrict__ A, const float* __restrict__ W,
    const float* __restrict__ bias, float* __restrict__ C,
    int M, int N, int K)
{
    gemm_tc_body(A, W, bias, C, M, N, K, N, blockIdx.y*128, blockIdx.x*128);
}

__global__ __launch_bounds__(256) void gemm_tcv(
    const float* __restrict__ V,
    const float* __restrict__ w0, const float* __restrict__ w1,
    const float* __restrict__ w2, const float* __restrict__ w3,
    float* __restrict__ C)
{
    const float* W = (blockIdx.z == 0) ? w0 : (blockIdx.z == 1) ? w1
                   : (blockIdx.z == 2) ? w2 : w3;
    gemm_tc_body(V, W, nullptr, C + blockIdx.z*HDIM,
                 NTOK, HDIM, DIM, 4*HDIM, blockIdx.y*128, blockIdx.x*128);
}

// ---------------- bit packing for boolean heads ----------------
__global__ void pack_bits()
{
    int gw = (blockIdx.x * blockDim.x + threadIdx.x) >> 5;
    int lane = threadIdx.x & 31;
    if (gw >= NTOK) return;
    unsigned q0 = __ballot_sync(0xffffffffu, g_qproj[(size_t)gw*PROJ + lane]       > 0.f);
    unsigned q1 = __ballot_sync(0xffffffffu, g_qproj[(size_t)gw*PROJ + 96 + lane]  > 0.f);
    unsigned k0 = __ballot_sync(0xffffffffu, g_kproj[(size_t)gw*PROJ + lane]       > 0.f);
    unsigned k1 = __ballot_sync(0xffffffffu, g_kproj[(size_t)gw*PROJ + 96 + lane]  > 0.f);
    if (lane == 0) {
        g_qbits[gw*2]   = q0; g_qbits[gw*2+1] = q1;
        g_kbits[gw*2]   = k0; g_kbits[gw*2+1] = k1;
    }
}

// ---------------- stage 1: scores (massively parallel, 64q x 64k tiles) ----
#define RE_STRIDE 34
#define TR_STRIDE 17

__global__ __launch_bounds__(256) void scores_kernel(
    const float* __restrict__ t_temp, const float* __restrict__ p_fusion)
{
    __shared__ float    qer[64*RE_STRIDE];
    __shared__ float    ker[64*RE_STRIDE];
    __shared__ __half2  qet[64*TR_STRIDE];
    __shared__ __half2  ket[64*TR_STRIDE];
    __shared__ unsigned qb[64], kb[64];

    const int k0  = blockIdx.x * 64;
    const int n0  = blockIdx.y * 64;
    const int bh  = blockIdx.z;
    const int b   = bh >> 2, head = bh & 3;
    const int tid = threadIdx.x;

    float inv_sp = 1.f;
    if (head == 1) inv_sp = 1.f / log1pf(expf(t_temp[0]));
    float fw0 = 0.f, fw1 = 0.f, fw2 = 0.f;
    if (head == 3) {
        float p0 = p_fusion[0], p1 = p_fusion[1], p2 = p_fusion[2];
        float mx = fmaxf(p0, fmaxf(p1, p2));
        float e0 = expf(p0-mx), e1 = expf(p1-mx), e2 = expf(p2-mx);
        float inv = 1.f/(e0+e1+e2);
        fw0 = e0*inv; fw1 = e1*inv; fw2 = e2*inv;
    }

    if (head == 0) {
        if (tid < 64)       qb[tid]    = g_qbits[(b*SEQ + n0 + tid)*2];
        else if (tid < 128) kb[tid-64] = g_kbits[(b*SEQ + k0 + tid-64)*2];
    } else if (head == 1) {
        for (int j = tid; j < 1024; j += 256) {
            int t = j >> 4, m = j & 15;
            const float* bq_ = &g_qproj[(size_t)(b*SEQ + n0 + t)*PROJ];
            const float* bk_ = &g_kproj[(size_t)(b*SEQ + k0 + t)*PROJ];
            qet[t*TR_STRIDE+m] = __floats2half2_rn(bq_[32+2*m], bq_[33+2*m]);
            ket[t*TR_STRIDE+m] = __floats2half2_rn(bk_[32+2*m], bk_[33+2*m]);
        }
    } else if (head == 2) {
        for (int j = tid; j < 2048; j += 256) {
            int t = j >> 5, m = j & 31;
            qer[t*RE_STRIDE+m] = g_qproj[(size_t)(b*SEQ + n0 + t)*PROJ + 64 + m];
            ker[t*RE_STRIDE+m] = g_kproj[(size_t)(b*SEQ + k0 + t)*PROJ + 64 + m];
        }
    } else {
        if (tid < 64)       qb[tid]    = g_qbits[(b*SEQ + n0 + tid)*2 + 1];
        else if (tid < 128) kb[tid-64] = g_kbits[(b*SEQ + k0 + tid-64)*2 + 1];
        for (int j = tid; j < 1024; j += 256) {
            int t = j >> 4, m = j & 15;
            const float* bq_ = &g_qproj[(size_t)(b*SEQ + n0 + t)*PROJ];
            const float* bk_ = &g_kproj[(size_t)(b*SEQ + k0 + t)*PROJ];
            qet[t*TR_STRIDE+m] = __floats2half2_rn(bq_[128+2*m], bq_[129+2*m]);
            ket[t*TR_STRIDE+m] = __floats2half2_rn(bk_[128+2*m], bk_[129+2*m]);
        }
        for (int j = tid; j < 2048; j += 256) {
            int t = j >> 5, m = j & 31;
            qer[t*RE_STRIDE+m] = g_qproj[(size_t)(b*SEQ + n0 + t)*PROJ + 160 + m];
            ker[t*RE_STRIDE+m] = g_kproj[(size_t)(b*SEQ + k0 + t)*PROJ + 160 + m];
        }
    }
    __syncthreads();

    const int kk    = tid & 63;
    const int qbase = (tid >> 6) * 16;
    float* Sout = g_S + ((size_t)bh << 20) + (size_t)(n0 + qbase)*1024 + k0 + kk;

    if (head == 0) {
        unsigned kr = kb[kk];
        #pragma unroll
        for (int i = 0; i < 16; ++i) {
            int p = __popc(qb[qbase+i] ^ kr);
            Sout[(size_t)i*1024] = (1.f - p*(1.f/32.f)) * SCALEF;
        }
    } else if (head == 1) {
        __half2 kr[16];
        const __half2* krow = &ket[kk*TR_STRIDE];
        #pragma unroll
        for (int m = 0; m < 16; ++m) kr[m] = krow[m];
        #pragma unroll 4
        for (int i = 0; i < 16; ++i) {
            const __half2* qe = &qet[(qbase+i)*TR_STRIDE];
            __half2 mnA = __hadd2(qe[0], kr[0]);
            __half2 mnB = __hadd2(qe[1], kr[1]);
            #pragma unroll
            for (int m = 2; m < 16; m += 2) {
                mnA = __hmin2(mnA, __hadd2(qe[m],   kr[m]));
                mnB = __hmin2(mnB, __hadd2(qe[m+1], kr[m+1]));
            }
            __half2 mn = __hmin2(mnA, mnB);
            float mnf = fminf(__low2float(mn), __high2float(mn));
            Sout[(size_t)i*1024] = -mnf * inv_sp;
        }
    } else if (head == 2) {
        float krr[32];
        const float* krow = &ker[kk*RE_STRIDE];
        #pragma unroll
        for (int m = 0; m < 32; ++m) krr[m] = krow[m];
        #pragma unroll 4
        for (int i = 0; i < 16; ++i) {
            const float* qe = &qer[(qbase+i)*RE_STRIDE];
            float da = 0.f, db = 0.f;
            #pragma unroll
            for (int m = 0; m < 32; m += 2) {
                da = fmaf(qe[m],   krr[m],   da);
                db = fmaf(qe[m+1], krr[m+1], db);
            }
            Sout[(size_t)i*1024] = (da + db) * SCALEF;
        }
    } else {
        __half2 krt[16];
        float krr[32];
        const __half2* ktrow = &ket[kk*TR_STRIDE];
        const float* krrow = &ker[kk*RE_STRIDE];
        #pragma unroll
        for (int m = 0; m < 16; ++m) krt[m] = ktrow[m];
        #pragma unroll
        for (int m = 0; m < 32; ++m) krr[m] = krrow[m];
        unsigned kr = kb[kk];
        #pragma unroll 2
        for (int i = 0; i < 16; ++i) {
            const __half2* qe = &qet[(qbase+i)*TR_STRIDE];
            const float* qf  = &qer[(qbase+i)*RE_STRIDE];
            __half2 mnA = __hadd2(qe[0], krt[0]);
            __half2 mnB = __hadd2(qe[1], krt[1]);
            float da = 0.f, db = 0.f;
            #pragma unroll
            for (int m = 2; m < 16; m += 2) {
                mnA = __hmin2(mnA, __hadd2(qe[m],   krt[m]));
                mnB = __hmin2(mnB, __hadd2(qe[m+1], krt[m+1]));
            }
            #pragma unroll
            for (int m = 0; m < 32; m += 2) {
                da = fmaf(qf[m],   krr[m],   da);
                db = fmaf(qf[m+1], krr[m+1], db);
            }
            __half2 mn = __hmin2(mnA, mnB);
            float mnf = fminf(__low2float(mn), __high2float(mn));
            float simb = 1.f - __popc(qb[qbase+i] ^ kr)*(1.f/32.f);
            Sout[(size_t)i*1024] = (fw0*simb - fw1*mnf + fw2*(da + db)) * SCALEF;
        }
    }
}

// ---------------- stage 2: row softmax stats (1 warp / row) ----------------
__device__ __forceinline__ float wredmax(float v) {
    #pragma unroll
    for (int o = 16; o; o >>= 1) v = fmaxf(v, __shfl_xor_sync(0xffffffffu, v, o));
    return v;
}
__device__ __forceinline__ float wredsum(float v) {
    #pragma unroll
    for (int o = 16; o; o >>= 1) v += __shfl_xor_sync(0xffffffffu, v, o);
    return v;
}

__global__ __launch_bounds__(256) void stats_kernel()
{
    int gw   = (blockIdx.x * blockDim.x + threadIdx.x) >> 5;  // row 0..8191
    int lane = threadIdx.x & 31;
    const float4* srow = (const float4*)(g_S + ((size_t)gw << 10));
    float4 v[8];
    float mx = -INFINITY;
    #pragma unroll
    for (int j = 0; j < 8; ++j) {
        v[j] = srow[j*32 + lane];
        mx = fmaxf(mx, fmaxf(fmaxf(v[j].x, v[j].y), fmaxf(v[j].z, v[j].w)));
    }
    mx = wredmax(mx);
    float s = 0.f;
    #pragma unroll
    for (int j = 0; j < 8; ++j)
        s += __expf(v[j].x-mx) + __expf(v[j].y-mx) + __expf(v[j].z-mx) + __expf(v[j].w-mx);
    s = wredsum(s);
    if (lane == 0) { g_m[gw] = mx; g_il[gw] = 1.f/s; }
}

// ---------------- stage 3: PV gemm with fused exp weighting ----------------
__global__ __launch_bounds__(256) void gemm_pv()
{
    __shared__ unsigned As[2][8][136];
    __shared__ unsigned Ws[2][8][136];

    const int bh = blockIdx.z, b = bh >> 2, head = bh & 3;
    const int bm = blockIdx.y * 128, bn = blockIdx.x * 128;
    const int tid = threadIdx.x;
    const int w = tid >> 5, lane = tid & 31;
    const int wm = w >> 2, wn = w & 3;
    const int qr = lane >> 2, qc = lane & 3;

    // A staging: S rows, exp-weighted
    const int lrow = tid >> 1, lc4 = (tid & 1) * 4;
    const float* Aptr = g_S + ((size_t)bh << 20) + (size_t)(bm + lrow)*1024 + lc4;
    const float mrow  = g_m [bh*1024 + bm + lrow];
    const float ilrow = g_il[bh*1024 + bm + lrow];

    // W staging: Vp tile rows k, cols head slice (natural [k][n] layout)
    const int kq = tid >> 5, n4 = tid & 31;
    const float* Wptr = g_Vp + (size_t)(b*SEQ + kq)*1024 + head*HDIM + bn + n4*4;

    float acc[4][4][4];
    #pragma unroll
    for (int i = 0; i < 4; ++i)
        #pragma unroll
        for (int j = 0; j < 4; ++j)
            #pragma unroll
            for (int r = 0; r < 4; ++r) acc[i][j][r] = 0.f;

    const int nt = 128;   // K=1024, BK=8
    float4 areg = *(const float4*)Aptr;
    float4 wreg = *(const float4*)Wptr;
    #pragma unroll
    for (int j = 0; j < 4; ++j) {
        As[0][lc4+j][lrow]  = f2tf32(__expf((&areg.x)[j] - mrow) * ilrow);
        Ws[0][kq][n4*4 + j] = f2tf32((&wreg.x)[j]);
    }
    __syncthreads();

    for (int t = 0; t < nt; ++t) {
        const int cur = t & 1;
        if (t + 1 < nt) {
            areg = *(const float4*)(Aptr + (t+1)*8);
            wreg = *(const float4*)(Wptr + (size_t)(t+1)*8*1024);
        }
        unsigned af[4][4], bf[4][2];
        #pragma unroll
        for (int i = 0; i < 4; ++i) {
            int m0 = wm*64 + i*16 + qr;
            af[i][0] = As[cur][qc  ][m0];
            af[i][1] = As[cur][qc  ][m0+8];
            af[i][2] = As[cur][qc+4][m0];
            af[i][3] = As[cur][qc+4][m0+8];
        }
        #pragma unroll
        for (int j = 0; j < 4; ++j) {
            int n0 = wn*32 + j*8 + qr;
            bf[j][0] = Ws[cur][qc  ][n0];
            bf[j][1] = Ws[cur][qc+4][n0];
        }
        #pragma unroll
        for (int i = 0; i < 4; ++i)
            #pragma unroll
            for (int j = 0; j < 4; ++j)
                mma_tf32(acc[i][j], af[i][0], af[i][1], af[i][2], af[i][3],
                         bf[j][0], bf[j][1]);
        if (t + 1 < nt) {
            const int nxt = cur ^ 1;
            #pragma unroll
            for (int j = 0; j < 4; ++j) {
                As[nxt][lc4+j][lrow]  = f2tf32(__expf((&areg.x)[j] - mrow) * ilrow);
                Ws[nxt][kq][n4*4 + j] = f2tf32((&wreg.x)[j]);
            }
        }
        __syncthreads();
    }

    float* Cb = g_cat + (size_t)(b*SEQ)*1024 + head*HDIM;
    #pragma unroll
    for (int i = 0; i < 4; ++i) {
        int r0 = bm + wm*64 + i*16 + qr;
        #pragma unroll
        for (int j = 0; j < 4; ++j) {
            int c0 = bn + wn*32 + j*8 + 2*qc;
            float2 o0, o1;
            o0.x = acc[i][j][0]; o0.y = acc[i][j][1];
            o1.x = acc[i][j][2]; o1.y = acc[i][j][3];
            *(float2*)&Cb[(size_t)r0*1024 + c0]     = o0;
            *(float2*)&Cb[(size_t)(r0+8)*1024 + c0] = o1;
        }
    }
}

// ---------------- host launch ----------------
extern "C" void kernel_launch(void* const* d_in, const int* in_sizes, int n_in,
                              void* d_out, int out_size)
{
    const float* Q        = (const float*)d_in[0];
    const float* K        = (const float*)d_in[1];
    const float* V        = (const float*)d_in[2];
    const float* bq_w     = (const float*)d_in[3];
    const float* bq_b     = (const float*)d_in[4];
    const float* bk_w     = (const float*)d_in[5];
    const float* bk_b     = (const float*)d_in[6];
    const float* b_v      = (const float*)d_in[7];
    const float* tq_w     = (const float*)d_in[8];
    const float* tq_b     = (const float*)d_in[9];
    const float* tk_w     = (const float*)d_in[10];
    const float* tk_b     = (const float*)d_in[11];
    const float* t_v      = (const float*)d_in[12];
    const float* t_temp   = (const float*)d_in[13];
    const float* rq_w     = (const float*)d_in[14];
    const float* rq_b     = (const float*)d_in[15];
    const float* rk_w     = (const float*)d_in[16];
    const float* rk_b     = (const float*)d_in[17];
    const float* r_v      = (const float*)d_in[18];
    const float* pq_w     = (const float*)d_in[19];
    const float* pq_b     = (const float*)d_in[20];
    const float* pk_w     = (const float*)d_in[21];
    const float* pk_b     = (const float*)d_in[22];
    const float* p_v      = (const float*)d_in[23];
    const float* p_fusion = (const float*)d_in[24];
    const float* out_w    = (const float*)d_in[25];
    const float* out_b    = (const float*)d_in[26];
    float* out = (float*)d_out;

    void *pWq, *pWk, *pBq, *pBk, *pqp, *pkp, *pVp, *pcat;
    cudaGetSymbolAddress(&pWq,  g_Wq);
    cudaGetSymbolAddress(&pWk,  g_Wk);
    cudaGetSymbolAddress(&pBq,  g_Bq);
    cudaGetSymbolAddress(&pBk,  g_Bk);
    cudaGetSymbolAddress(&pqp,  g_qproj);
    cudaGetSymbolAddress(&pkp,  g_kproj);
    cudaGetSymbolAddress(&pVp,  g_Vp);
    cudaGetSymbolAddress(&pcat, g_cat);

    pack_weights<<<128, 256>>>(bq_w, tq_w, rq_w, pq_w, bq_b, tq_b, rq_b, pq_b,
                               bk_w, tk_w, rk_w, pk_w, bk_b, tk_b, rk_b, pk_b);

    // Q/K projections (exact fp32): [2048 x 192 x 1024], z selects Q/K
    gemm_db<64,4><<<dim3(2, 32, 2), 256>>>(
        Q, K, (const float*)pWq, (const float*)pWk,
        (const float*)pBq, (const float*)pBk,
        (float*)pqp, (float*)pkp, NTOK, PROJ, DIM);

    // V projection (tf32, per head via z; writes strided into g_Vp)
    gemm_tcv<<<dim3(2, 16, 4), 256>>>(V, b_v, t_v, r_v, p_v, (float*)pVp);

    pack_bits<<<NTOK*32/256, 256>>>();

    // stage 1: all scores (2048 blocks, high occupancy)
    scores_kernel<<<dim3(16, 16, 8), 256>>>(t_temp, p_fusion);

    // stage 2: exact softmax stats (1 warp per row)
    stats_kernel<<<1024, 256>>>();

    // stage 3: exp-weighted PV tensor-core GEMM -> g_cat
    gemm_pv<<<dim3(2, 8, 8), 256>>>();

    // output projection (tf32 tensor cores): [2048 x 1024 x 1024]
    gemm_tc<<<dim3(8, 16), 256>>>((const float*)pcat, out_w, out_b,
                                  out, NTOK, DIM, DIM);
}

// round 8
// speedup vs baseline: 1.2066x; 1.1425x over previous
#include <cuda_runtime.h>
#include <cuda_fp16.h>
#include <math.h>

// ---------------- problem constants ----------------
#define BATCH 2
#define SEQ   1024
#define DIM   1024
#define HDIM  256
#define MBITS 32
#define NTOK  (BATCH*SEQ)     // 2048
#define PROJ  192             // 6 groups x 32
#define SCALEF 0.17677669529663687f  // 1/sqrt(32)

// ---------------- device scratch (static, no allocs) ----------------
__device__ float    g_Wq[PROJ*DIM];
__device__ float    g_Wk[PROJ*DIM];
__device__ float    g_Bq[PROJ];
__device__ float    g_Bk[PROJ];
__device__ float    g_qproj[NTOK*PROJ];
__device__ float    g_kproj[NTOK*PROJ];
__device__ unsigned g_qbits[NTOK*2];
__device__ unsigned g_kbits[NTOK*2];
__device__ float    g_Vp[NTOK*4*HDIM];
__device__ float    g_cat[NTOK*4*HDIM];
__device__ float    g_S[8u*1024u*1024u];   // [b*4+head][q][k] scores, 32MB
__device__ float    g_m[8*1024];           // row max
__device__ float    g_il[8*1024];          // 1/row sumexp

// ---------------- pack Q/K projection weights ----------------
__global__ void pack_weights(
    const float* __restrict__ bq_w, const float* __restrict__ tq_w,
    const float* __restrict__ rq_w, const float* __restrict__ pq_w,
    const float* __restrict__ bq_b, const float* __restrict__ tq_b,
    const float* __restrict__ rq_b, const float* __restrict__ pq_b,
    const float* __restrict__ bk_w, const float* __restrict__ tk_w,
    const float* __restrict__ rk_w, const float* __restrict__ pk_w,
    const float* __restrict__ bk_b, const float* __restrict__ tk_b,
    const float* __restrict__ rk_b, const float* __restrict__ pk_b)
{
    int i0 = blockIdx.x * blockDim.x + threadIdx.x;
    int stride = gridDim.x * blockDim.x;
    for (int e = i0; e < PROJ*DIM; e += stride) {
        int r = e >> 10, d = e & 1023;
        int g = r >> 5, j = r & 31;
        const float* sq; const float* sk;
        switch (g) {
            case 0: sq = bq_w; sk = bk_w; break;
            case 1: sq = tq_w; sk = tk_w; break;
            case 2: sq = rq_w; sk = rk_w; break;
            default: sq = pq_w + (g-3)*MBITS*DIM; sk = pk_w + (g-3)*MBITS*DIM; break;
        }
        int off = j*DIM + d;
        g_Wq[e] = sq[off];
        g_Wk[e] = sk[off];
    }
    for (int e = i0; e < PROJ; e += stride) {
        int g = e >> 5, j = e & 31;
        float vq, vk;
        switch (g) {
            case 0: vq = bq_b[j]; vk = bk_b[j]; break;
            case 1: vq = tq_b[j]; vk = tk_b[j]; break;
            case 2: vq = rq_b[j]; vk = rk_b[j]; break;
            default: vq = pq_b[(g-3)*MBITS + j]; vk = pk_b[(g-3)*MBITS + j]; break;
        }
        g_Bq[e] = vq;
        g_Bk[e] = vk;
    }
}

// ---------------- fp32 QK projection GEMM: 64x64 tiles, grid (3,32,2) ------
__global__ __launch_bounds__(256) void gemm_qk(
    const float* __restrict__ Qin, const float* __restrict__ Kin)
{
    __shared__ __align__(16) float As[2][8][68];
    __shared__ __align__(16) float Ws[2][8][68];

    const float* A    = blockIdx.z ? Kin : Qin;
    const float* W    = blockIdx.z ? g_Wk : g_Wq;
    const float* bias = blockIdx.z ? g_Bk : g_Bq;
    float*       C    = blockIdx.z ? g_kproj : g_qproj;

    const int bm = blockIdx.y * 64, bn = blockIdx.x * 64;
    const int tid = threadIdx.x;
    const int tx = tid & 15, ty = tid >> 4;

    const bool isA = tid < 128;
    const int st = isA ? tid : tid - 128;
    const int srow = st >> 1, sc4 = (st & 1) * 4;
    const float* Sptr = isA ? A + (size_t)(bm + srow)*DIM + sc4
                            : W + (size_t)(bn + srow)*DIM + sc4;

    float acc[4][4];
    #pragma unroll
    for (int i = 0; i < 4; ++i)
        #pragma unroll
        for (int j = 0; j < 4; ++j) acc[i][j] = 0.f;

    const int nt = DIM >> 3;  // 128
    float4 sreg = *(const float4*)Sptr;
    #pragma unroll
    for (int j = 0; j < 4; ++j) {
        if (isA) As[0][sc4+j][srow] = (&sreg.x)[j];
        else     Ws[0][sc4+j][srow] = (&sreg.x)[j];
    }
    __syncthreads();

    for (int t = 0; t < nt; ++t) {
        const int cur = t & 1;
        if (t + 1 < nt) sreg = *(const float4*)(Sptr + (t+1)*8);
        #pragma unroll
        for (int kk = 0; kk < 8; ++kk) {
            float4 a4 = *(const float4*)&As[cur][kk][ty*4];
            float4 b4 = *(const float4*)&Ws[cur][kk][tx*4];
            const float* a = &a4.x;
            const float* b = &b4.x;
            #pragma unroll
            for (int i = 0; i < 4; ++i)
                #pragma unroll
                for (int j = 0; j < 4; ++j)
                    acc[i][j] += a[i]*b[j];
        }
        if (t + 1 < nt) {
            const int nxt = cur ^ 1;
            #pragma unroll
            for (int j = 0; j < 4; ++j) {
                if (isA) As[nxt][sc4+j][srow] = (&sreg.x)[j];
                else     Ws[nxt][sc4+j][srow] = (&sreg.x)[j];
            }
        }
        __syncthreads();
    }

    #pragma unroll
    for (int i = 0; i < 4; ++i) {
        int row = bm + ty*4 + i;
        int col = bn + tx*4;
        float4 o;
        o.x = acc[i][0] + bias[col];
        o.y = acc[i][1] + bias[col+1];
        o.z = acc[i][2] + bias[col+2];
        o.w = acc[i][3] + bias[col+3];
        *(float4*)&C[(size_t)row*PROJ + col] = o;
    }
}

// ---------------- tf32 helpers ----------------
__device__ __forceinline__ unsigned f2tf32(float f) {
    unsigned u;
    asm("cvt.rna.tf32.f32 %0, %1;" : "=r"(u) : "f"(f));
    return u;
}
__device__ __forceinline__ void mma_tf32(float c[4],
    unsigned a0, unsigned a1, unsigned a2, unsigned a3,
    unsigned b0, unsigned b1)
{
    asm("mma.sync.aligned.m16n8k8.row.col.f32.tf32.tf32.f32 "
        "{%0,%1,%2,%3},{%4,%5,%6,%7},{%8,%9},{%0,%1,%2,%3};"
        : "+f"(c[0]), "+f"(c[1]), "+f"(c[2]), "+f"(c[3])
        : "r"(a0), "r"(a1), "r"(a2), "r"(a3), "r"(b0), "r"(b1));
}

// ---------------- 512-thread tf32 GEMM core: 128x128 tile, 16 warps -------
// A[M,K] row-major, W[N,K] row-major (B^T), C row-major ldc.
__device__ __forceinline__ void tc512_core(
    const float* __restrict__ A, const float* __restrict__ W,
    const float* __restrict__ bias, float* __restrict__ C,
    int K, int ldc, int bm, int bn)
{
    __shared__ unsigned As[2][8][136];
    __shared__ unsigned Ws[2][8][136];

    const int tid = threadIdx.x;
    const int w = tid >> 5, lane = tid & 31;
    const int wm = w >> 2, wn = w & 3;          // 4x4 warp grid, 32x32 tiles
    const int qr = lane >> 2, qc = lane & 3;

    const bool isA = tid < 256;
    const int st = isA ? tid : tid - 256;
    const int srow = st >> 1, sc4 = (st & 1) * 4;
    const float* Sptr = isA ? A + (size_t)(bm + srow)*K + sc4
                            : W + (size_t)(bn + srow)*K + sc4;

    float acc[2][4][4];
    #pragma unroll
    for (int i = 0; i < 2; ++i)
        #pragma unroll
        for (int j = 0; j < 4; ++j)
            #pragma unroll
            for (int r = 0; r < 4; ++r) acc[i][j][r] = 0.f;

    const int nt = K >> 3;
    float4 sreg = *(const float4*)Sptr;
    #pragma unroll
    for (int j = 0; j < 4; ++j) {
        if (isA) As[0][sc4+j][srow] = f2tf32((&sreg.x)[j]);
        else     Ws[0][sc4+j][srow] = f2tf32((&sreg.x)[j]);
    }
    __syncthreads();

    for (int t = 0; t < nt; ++t) {
        const int cur = t & 1;
        if (t + 1 < nt) sreg = *(const float4*)(Sptr + (t+1)*8);
        unsigned af[2][4], bf[4][2];
        #pragma unroll
        for (int i = 0; i < 2; ++i) {
            int m0 = wm*32 + i*16 + qr;
            af[i][0] = As[cur][qc  ][m0];
            af[i][1] = As[cur][qc  ][m0+8];
            af[i][2] = As[cur][qc+4][m0];
            af[i][3] = As[cur][qc+4][m0+8];
        }
        #pragma unroll
        for (int j = 0; j < 4; ++j) {
            int n0 = wn*32 + j*8 + qr;
            bf[j][0] = Ws[cur][qc  ][n0];
            bf[j][1] = Ws[cur][qc+4][n0];
        }
        #pragma unroll
        for (int i = 0; i < 2; ++i)
            #pragma unroll
            for (int j = 0; j < 4; ++j)
                mma_tf32(acc[i][j], af[i][0], af[i][1], af[i][2], af[i][3],
                         bf[j][0], bf[j][1]);
        if (t + 1 < nt) {
            const int nxt = cur ^ 1;
            #pragma unroll
            for (int j = 0; j < 4; ++j) {
                if (isA) As[nxt][sc4+j][srow] = f2tf32((&sreg.x)[j]);
                else     Ws[nxt][sc4+j][srow] = f2tf32((&sreg.x)[j]);
            }
        }
        __syncthreads();
    }

    #pragma unroll
    for (int i = 0; i < 2; ++i) {
        int r0 = bm + wm*32 + i*16 + qr;
        #pragma unroll
        for (int j = 0; j < 4; ++j) {
            int c0 = bn + wn*32 + j*8 + 2*qc;
            float bx = 0.f, by = 0.f;
            if (bias) { bx = bias[c0]; by = bias[c0+1]; }
            float2 o0, o1;
            o0.x = acc[i][j][0] + bx; o0.y = acc[i][j][1] + by;
            o1.x = acc[i][j][2] + bx; o1.y = acc[i][j][3] + by;
            *(float2*)&C[(size_t)r0*ldc + c0]     = o0;
            *(float2*)&C[(size_t)(r0+8)*ldc + c0] = o1;
        }
    }
}

// out-proj: C[2048,1024] = cat * out_w^T + out_b
__global__ __launch_bounds__(512) void gemm_tc512(
    const float* __restrict__ A, const float* __restrict__ W,
    const float* __restrict__ bias, float* __restrict__ C,
    int K, int ldc)
{
    tc512_core(A, W, bias, C, K, ldc, blockIdx.y*128, blockIdx.x*128);
}

// V projection per head (z selects head weight), strided output into g_Vp
__global__ __launch_bounds__(512) void gemm_tcv512(
    const float* __restrict__ V,
    const float* __restrict__ w0, const float* __restrict__ w1,
    const float* __restrict__ w2, const float* __restrict__ w3,
    float* __restrict__ C)
{
    const float* W = (blockIdx.z == 0) ? w0 : (blockIdx.z == 1) ? w1
                   : (blockIdx.z == 2) ? w2 : w3;
    tc512_core(V, W, nullptr, C + blockIdx.z*HDIM,
               DIM, 4*HDIM, blockIdx.y*128, blockIdx.x*128);
}

// ---------------- PV GEMM, 512 threads, fused exp weighting ----------------
__global__ __launch_bounds__(512) void gemm_pv512()
{
    __shared__ unsigned As[2][8][136];
    __shared__ unsigned Ws[2][8][136];

    const int bh = blockIdx.z, b = bh >> 2, head = bh & 3;
    const int bm = blockIdx.y * 128, bn = blockIdx.x * 128;
    const int tid = threadIdx.x;
    const int w = tid >> 5, lane = tid & 31;
    const int wm = w >> 2, wn = w & 3;
    const int qr = lane >> 2, qc = lane & 3;

    // staging roles
    const bool isA = tid < 256;
    const int st = isA ? tid : tid - 256;
    // A: S rows, exp-weighted
    const int lrow = st >> 1, lc4 = (st & 1) * 4;
    const float* Aptr = g_S + ((size_t)bh << 20) + (size_t)(bm + lrow)*1024 + lc4;
    const float mrow  = g_m [bh*1024 + bm + lrow];
    const float ilrow = g_il[bh*1024 + bm + lrow];
    // W: Vp k-major rows
    const int kq = st >> 5, n4 = st & 31;
    const float* Wptr = g_Vp + (size_t)(b*SEQ + kq)*1024 + head*HDIM + bn + n4*4;

    float acc[2][4][4];
    #pragma unroll
    for (int i = 0; i < 2; ++i)
        #pragma unroll
        for (int j = 0; j < 4; ++j)
            #pragma unroll
            for (int r = 0; r < 4; ++r) acc[i][j][r] = 0.f;

    const int nt = 128;
    float4 sreg = isA ? *(const float4*)Aptr : *(const float4*)Wptr;
    if (isA) {
        #pragma unroll
        for (int j = 0; j < 4; ++j)
            As[0][lc4+j][lrow] = f2tf32(__expf((&sreg.x)[j] - mrow) * ilrow);
    } else {
        uint4 pk;
        pk.x = f2tf32(sreg.x); pk.y = f2tf32(sreg.y);
        pk.z = f2tf32(sreg.z); pk.w = f2tf32(sreg.w);
        *(uint4*)&Ws[0][kq][n4*4] = pk;
    }
    __syncthreads();

    for (int t = 0; t < nt; ++t) {
        const int cur = t & 1;
        if (t + 1 < nt)
            sreg = isA ? *(const float4*)(Aptr + (t+1)*8)
                       : *(const float4*)(Wptr + (size_t)(t+1)*8*1024);
        unsigned af[2][4], bf[4][2];
        #pragma unroll
        for (int i = 0; i < 2; ++i) {
            int m0 = wm*32 + i*16 + qr;
            af[i][0] = As[cur][qc  ][m0];
            af[i][1] = As[cur][qc  ][m0+8];
            af[i][2] = As[cur][qc+4][m0];
            af[i][3] = As[cur][qc+4][m0+8];
        }
        #pragma unroll
        for (int j = 0; j < 4; ++j) {
            int n0 = wn*32 + j*8 + qr;
            bf[j][0] = Ws[cur][qc  ][n0];
            bf[j][1] = Ws[cur][qc+4][n0];
        }
        #pragma unroll
        for (int i = 0; i < 2; ++i)
            #pragma unroll
            for (int j = 0; j < 4; ++j)
                mma_tf32(acc[i][j], af[i][0], af[i][1], af[i][2], af[i][3],
                         bf[j][0], bf[j][1]);
        if (t + 1 < nt) {
            const int nxt = cur ^ 1;
            if (isA) {
                #pragma unroll
                for (int j = 0; j < 4; ++j)
                    As[nxt][lc4+j][lrow] = f2tf32(__expf((&sreg.x)[j] - mrow) * ilrow);
            } else {
                uint4 pk;
                pk.x = f2tf32(sreg.x); pk.y = f2tf32(sreg.y);
                pk.z = f2tf32(sreg.z); pk.w = f2tf32(sreg.w);
                *(uint4*)&Ws[nxt][kq][n4*4] = pk;
            }
        }
        __syncthreads();
    }

    float* Cb = g_cat + (size_t)(b*SEQ)*1024 + head*HDIM;
    #pragma unroll
    for (int i = 0; i < 2; ++i) {
        int r0 = bm + wm*32 + i*16 + qr;
        #pragma unroll
        for (int j = 0; j < 4; ++j) {
            int c0 = bn + wn*32 + j*8 + 2*qc;
            float2 o0, o1;
            o0.x = acc[i][j][0]; o0.y = acc[i][j][1];
            o1.x = acc[i][j][2]; o1.y = acc[i][j][3];
            *(float2*)&Cb[(size_t)r0*1024 + c0]     = o0;
            *(float2*)&Cb[(size_t)(r0+8)*1024 + c0] = o1;
        }
    }
}

// ---------------- bit packing for boolean heads ----------------
__global__ void pack_bits()
{
    int gw = (blockIdx.x * blockDim.x + threadIdx.x) >> 5;
    int lane = threadIdx.x & 31;
    if (gw >= NTOK) return;
    unsigned q0 = __ballot_sync(0xffffffffu, g_qproj[(size_t)gw*PROJ + lane]       > 0.f);
    unsigned q1 = __ballot_sync(0xffffffffu, g_qproj[(size_t)gw*PROJ + 96 + lane]  > 0.f);
    unsigned k0 = __ballot_sync(0xffffffffu, g_kproj[(size_t)gw*PROJ + lane]       > 0.f);
    unsigned k1 = __ballot_sync(0xffffffffu, g_kproj[(size_t)gw*PROJ + 96 + lane]  > 0.f);
    if (lane == 0) {
        g_qbits[gw*2]   = q0; g_qbits[gw*2+1] = q1;
        g_kbits[gw*2]   = k0; g_kbits[gw*2+1] = k1;
    }
}

// ---------------- stage 1: scores (massively parallel, 64q x 64k tiles) ----
#define RE_STRIDE 34
#define TR_STRIDE 17

__global__ __launch_bounds__(256) void scores_kernel(
    const float* __restrict__ t_temp, const float* __restrict__ p_fusion)
{
    __shared__ float    qer[64*RE_STRIDE];
    __shared__ float    ker[64*RE_STRIDE];
    __shared__ __half2  qet[64*TR_STRIDE];
    __shared__ __half2  ket[64*TR_STRIDE];
    __shared__ unsigned qb[64], kb[64];

    const int k0  = blockIdx.x * 64;
    const int n0  = blockIdx.y * 64;
    const int bh  = blockIdx.z;
    const int b   = bh >> 2, head = bh & 3;
    const int tid = threadIdx.x;

    float inv_sp = 1.f;
    if (head == 1) inv_sp = 1.f / log1pf(expf(t_temp[0]));
    float fw0 = 0.f, fw1 = 0.f, fw2 = 0.f;
    if (head == 3) {
        float p0 = p_fusion[0], p1 = p_fusion[1], p2 = p_fusion[2];
        float mx = fmaxf(p0, fmaxf(p1, p2));
        float e0 = expf(p0-mx), e1 = expf(p1-mx), e2 = expf(p2-mx);
        float inv = 1.f/(e0+e1+e2);
        fw0 = e0*inv; fw1 = e1*inv; fw2 = e2*inv;
    }

    if (head == 0) {
        if (tid < 64)       qb[tid]    = g_qbits[(b*SEQ + n0 + tid)*2];
        else if (tid < 128) kb[tid-64] = g_kbits[(b*SEQ + k0 + tid-64)*2];
    } else if (head == 1) {
        for (int j = tid; j < 1024; j += 256) {
            int t = j >> 4, m = j & 15;
            const float* bq_ = &g_qproj[(size_t)(b*SEQ + n0 + t)*PROJ];
            const float* bk_ = &g_kproj[(size_t)(b*SEQ + k0 + t)*PROJ];
            qet[t*TR_STRIDE+m] = __floats2half2_rn(bq_[32+2*m], bq_[33+2*m]);
            ket[t*TR_STRIDE+m] = __floats2half2_rn(bk_[32+2*m], bk_[33+2*m]);
        }
    } else if (head == 2) {
        for (int j = tid; j < 2048; j += 256) {
            int t = j >> 5, m = j & 31;
            qer[t*RE_STRIDE+m] = g_qproj[(size_t)(b*SEQ + n0 + t)*PROJ + 64 + m];
            ker[t*RE_STRIDE+m] = g_kproj[(size_t)(b*SEQ + k0 + t)*PROJ + 64 + m];
        }
    } else {
        if (tid < 64)       qb[tid]    = g_qbits[(b*SEQ + n0 + tid)*2 + 1];
        else if (tid < 128) kb[tid-64] = g_kbits[(b*SEQ + k0 + tid-64)*2 + 1];
        for (int j = tid; j < 1024; j += 256) {
            int t = j >> 4, m = j & 15;
            const float* bq_ = &g_qproj[(size_t)(b*SEQ + n0 + t)*PROJ];
            const float* bk_ = &g_kproj[(size_t)(b*SEQ + k0 + t)*PROJ];
            qet[t*TR_STRIDE+m] = __floats2half2_rn(bq_[128+2*m], bq_[129+2*m]);
            ket[t*TR_STRIDE+m] = __floats2half2_rn(bk_[128+2*m], bk_[129+2*m]);
        }
        for (int j = tid; j < 2048; j += 256) {
            int t = j >> 5, m = j & 31;
            qer[t*RE_STRIDE+m] = g_qproj[(size_t)(b*SEQ + n0 + t)*PROJ + 160 + m];
            ker[t*RE_STRIDE+m] = g_kproj[(size_t)(b*SEQ + k0 + t)*PROJ + 160 + m];
        }
    }
    __syncthreads();

    const int kk    = tid & 63;
    const int qbase = (tid >> 6) * 16;
    float* Sout = g_S + ((size_t)bh << 20) + (size_t)(n0 + qbase)*1024 + k0 + kk;

    if (head == 0) {
        unsigned kr = kb[kk];
        #pragma unroll
        for (int i = 0; i < 16; ++i) {
            int p = __popc(qb[qbase+i] ^ kr);
            Sout[(size_t)i*1024] = (1.f - p*(1.f/32.f)) * SCALEF;
        }
    } else if (head == 1) {
        __half2 kr[16];
        const __half2* krow = &ket[kk*TR_STRIDE];
        #pragma unroll
        for (int m = 0; m < 16; ++m) kr[m] = krow[m];
        #pragma unroll 4
        for (int i = 0; i < 16; ++i) {
            const __half2* qe = &qet[(qbase+i)*TR_STRIDE];
            __half2 mnA = __hadd2(qe[0], kr[0]);
            __half2 mnB = __hadd2(qe[1], kr[1]);
            #pragma unroll
            for (int m = 2; m < 16; m += 2) {
                mnA = __hmin2(mnA, __hadd2(qe[m],   kr[m]));
                mnB = __hmin2(mnB, __hadd2(qe[m+1], kr[m+1]));
            }
            __half2 mn = __hmin2(mnA, mnB);
            float mnf = fminf(__low2float(mn), __high2float(mn));
            Sout[(size_t)i*1024] = -mnf * inv_sp;
        }
    } else if (head == 2) {
        float krr[32];
        const float* krow = &ker[kk*RE_STRIDE];
        #pragma unroll
        for (int m = 0; m < 32; ++m) krr[m] = krow[m];
        #pragma unroll 4
        for (int i = 0; i < 16; ++i) {
            const float* qe = &qer[(qbase+i)*RE_STRIDE];
            float da = 0.f, db = 0.f;
            #pragma unroll
            for (int m = 0; m < 32; m += 2) {
                da = fmaf(qe[m],   krr[m],   da);
                db = fmaf(qe[m+1], krr[m+1], db);
            }
            Sout[(size_t)i*1024] = (da + db) * SCALEF;
        }
    } else {
        __half2 krt[16];
        float krr[32];
        const __half2* ktrow = &ket[kk*TR_STRIDE];
        const float* krrow = &ker[kk*RE_STRIDE];
        #pragma unroll
        for (int m = 0; m < 16; ++m) krt[m] = ktrow[m];
        #pragma unroll
        for (int m = 0; m < 32; ++m) krr[m] = krrow[m];
        unsigned kr = kb[kk];
        #pragma unroll 2
        for (int i = 0; i < 16; ++i) {
            const __half2* qe = &qet[(qbase+i)*TR_STRIDE];
            const float* qf  = &qer[(qbase+i)*RE_STRIDE];
            __half2 mnA = __hadd2(qe[0], krt[0]);
            __half2 mnB = __hadd2(qe[1], krt[1]);
            float da = 0.f, db = 0.f;
            #pragma unroll
            for (int m = 2; m < 16; m += 2) {
                mnA = __hmin2(mnA, __hadd2(qe[m],   krt[m]));
                mnB = __hmin2(mnB, __hadd2(qe[m+1], krt[m+1]));
            }
            #pragma unroll
            for (int m = 0; m < 32; m += 2) {
                da = fmaf(qf[m],   krr[m],   da);
                db = fmaf(qf[m+1], krr[m+1], db);
            }
            __half2 mn = __hmin2(mnA, mnB);
            float mnf = fminf(__low2float(mn), __high2float(mn));
            float simb = 1.f - __popc(qb[qbase+i] ^ kr)*(1.f/32.f);
            Sout[(size_t)i*1024] = (fw0*simb - fw1*mnf + fw2*(da + db)) * SCALEF;
        }
    }
}

// ---------------- stage 2: row softmax stats (1 warp / row) ----------------
__device__ __forceinline__ float wredmax(float v) {
    #pragma unroll
    for (int o = 16; o; o >>= 1) v = fmaxf(v, __shfl_xor_sync(0xffffffffu, v, o));
    return v;
}
__device__ __forceinline__ float wredsum(float v) {
    #pragma unroll
    for (int o = 16; o; o >>= 1) v += __shfl_xor_sync(0xffffffffu, v, o);
    return v;
}

__global__ __launch_bounds__(256) void stats_kernel()
{
    int gw   = (blockIdx.x * blockDim.x + threadIdx.x) >> 5;  // row 0..8191
    int lane = threadIdx.x & 31;
    const float4* srow = (const float4*)(g_S + ((size_t)gw << 10));
    float4 v[8];
    float mx = -INFINITY;
    #pragma unroll
    for (int j = 0; j < 8; ++j) {
        v[j] = srow[j*32 + lane];
        mx = fmaxf(mx, fmaxf(fmaxf(v[j].x, v[j].y), fmaxf(v[j].z, v[j].w)));
    }
    mx = wredmax(mx);
    float s = 0.f;
    #pragma unroll
    for (int j = 0; j < 8; ++j)
        s += __expf(v[j].x-mx) + __expf(v[j].y-mx) + __expf(v[j].z-mx) + __expf(v[j].w-mx);
    s = wredsum(s);
    if (lane == 0) { g_m[gw] = mx; g_il[gw] = 1.f/s; }
}

// ---------------- host launch ----------------
extern "C" void kernel_launch(void* const* d_in, const int* in_sizes, int n_in,
                              void* d_out, int out_size)
{
    const float* Q        = (const float*)d_in[0];
    const float* K        = (const float*)d_in[1];
    const float* V        = (const float*)d_in[2];
    const float* bq_w     = (const float*)d_in[3];
    const float* bq_b     = (const float*)d_in[4];
    const float* bk_w     = (const float*)d_in[5];
    const float* bk_b     = (const float*)d_in[6];
    const float* b_v      = (const float*)d_in[7];
    const float* tq_w     = (const float*)d_in[8];
    const float* tq_b     = (const float*)d_in[9];
    const float* tk_w     = (const float*)d_in[10];
    const float* tk_b     = (const float*)d_in[11];
    const float* t_v      = (const float*)d_in[12];
    const float* t_temp   = (const float*)d_in[13];
    const float* rq_w     = (const float*)d_in[14];
    const float* rq_b     = (const float*)d_in[15];
    const float* rk_w     = (const float*)d_in[16];
    const float* rk_b     = (const float*)d_in[17];
    const float* r_v      = (const float*)d_in[18];
    const float* pq_w     = (const float*)d_in[19];
    const float* pq_b     = (const float*)d_in[20];
    const float* pk_w     = (const float*)d_in[21];
    const float* pk_b     = (const float*)d_in[22];
    const float* p_v      = (const float*)d_in[23];
    const float* p_fusion = (const float*)d_in[24];
    const float* out_w    = (const float*)d_in[25];
    const float* out_b    = (const float*)d_in[26];
    float* out = (float*)d_out;

    void *pVp, *pcat;
    cudaGetSymbolAddress(&pVp,  g_Vp);
    cudaGetSymbolAddress(&pcat, g_cat);

    pack_weights<<<128, 256>>>(bq_w, tq_w, rq_w, pq_w, bq_b, tq_b, rq_b, pq_b,
                               bk_w, tk_w, rk_w, pk_w, bk_b, tk_b, rk_b, pk_b);

    // Q/K projections (exact fp32): 64x64 tiles, grid 192
    gemm_qk<<<dim3(3, 32, 2), 256>>>(Q, K);

    // V projection (tf32, per head via z; strided into g_Vp)
    gemm_tcv512<<<dim3(2, 16, 4), 512>>>(V, b_v, t_v, r_v, p_v, (float*)pVp);

    pack_bits<<<NTOK*32/256, 256>>>();

    // stage 1: all scores
    scores_kernel<<<dim3(16, 16, 8), 256>>>(t_temp, p_fusion);

    // stage 2: exact softmax stats
    stats_kernel<<<1024, 256>>>();

    // stage 3: exp-weighted PV tensor-core GEMM -> g_cat
    gemm_pv512<<<dim3(2, 8, 8), 512>>>();

    // output projection
    gemm_tc512<<<dim3(8, 16), 512>>>((const float*)pcat, out_w, out_b,
                                     out, DIM, DIM);
}

// round 9
// speedup vs baseline: 1.4386x; 1.1922x over previous
#include <cuda_runtime.h>
#include <cuda_fp16.h>
#include <math.h>

// ---------------- problem constants ----------------
#define BATCH 2
#define SEQ   1024
#define DIM   1024
#define HDIM  256
#define MBITS 32
#define NTOK  (BATCH*SEQ)     // 2048
#define PROJ  192             // 6 groups x 32
#define SCALEF 0.17677669529663687f  // 1/sqrt(32)

// ---------------- device scratch (static, no allocs) ----------------
__device__ float    g_Wq[PROJ*DIM];
__device__ float    g_Wk[PROJ*DIM];
__device__ float    g_Bq[PROJ];
__device__ float    g_Bk[PROJ];
__device__ float    g_qproj[NTOK*PROJ];
__device__ float    g_kproj[NTOK*PROJ];
__device__ unsigned g_qbits[NTOK*2];
__device__ unsigned g_kbits[NTOK*2];
__device__ float    g_Vp[NTOK*4*HDIM];
__device__ float    g_cat[NTOK*4*HDIM];
__device__ float    g_S[8u*1024u*1024u];   // [b*4+head][q][k] scores, 32MB
__device__ float    g_m[8*1024];           // row max
__device__ float    g_il[8*1024];          // 1/row sumexp

// ---------------- pack Q/K projection weights ----------------
__global__ void pack_weights(
    const float* __restrict__ bq_w, const float* __restrict__ tq_w,
    const float* __restrict__ rq_w, const float* __restrict__ pq_w,
    const float* __restrict__ bq_b, const float* __restrict__ tq_b,
    const float* __restrict__ rq_b, const float* __restrict__ pq_b,
    const float* __restrict__ bk_w, const float* __restrict__ tk_w,
    const float* __restrict__ rk_w, const float* __restrict__ pk_w,
    const float* __restrict__ bk_b, const float* __restrict__ tk_b,
    const float* __restrict__ rk_b, const float* __restrict__ pk_b)
{
    int i0 = blockIdx.x * blockDim.x + threadIdx.x;
    int stride = gridDim.x * blockDim.x;
    for (int e = i0; e < PROJ*DIM; e += stride) {
        int r = e >> 10, d = e & 1023;
        int g = r >> 5, j = r & 31;
        const float* sq; const float* sk;
        switch (g) {
            case 0: sq = bq_w; sk = bk_w; break;
            case 1: sq = tq_w; sk = tk_w; break;
            case 2: sq = rq_w; sk = rk_w; break;
            default: sq = pq_w + (g-3)*MBITS*DIM; sk = pk_w + (g-3)*MBITS*DIM; break;
        }
        int off = j*DIM + d;
        g_Wq[e] = sq[off];
        g_Wk[e] = sk[off];
    }
    for (int e = i0; e < PROJ; e += stride) {
        int g = e >> 5, j = e & 31;
        float vq, vk;
        switch (g) {
            case 0: vq = bq_b[j]; vk = bk_b[j]; break;
            case 1: vq = tq_b[j]; vk = tk_b[j]; break;
            case 2: vq = rq_b[j]; vk = rk_b[j]; break;
            default: vq = pq_b[(g-3)*MBITS + j]; vk = pk_b[(g-3)*MBITS + j]; break;
        }
        g_Bq[e] = vq;
        g_Bk[e] = vk;
    }
}

// ---------------- fp32 QK projection GEMM: 64x64 tiles, grid (3,32,2) ------
__global__ __launch_bounds__(256) void gemm_qk(
    const float* __restrict__ Qin, const float* __restrict__ Kin)
{
    __shared__ __align__(16) float As[2][8][68];
    __shared__ __align__(16) float Ws[2][8][68];

    const float* A    = blockIdx.z ? Kin : Qin;
    const float* W    = blockIdx.z ? g_Wk : g_Wq;
    const float* bias = blockIdx.z ? g_Bk : g_Bq;
    float*       C    = blockIdx.z ? g_kproj : g_qproj;

    const int bm = blockIdx.y * 64, bn = blockIdx.x * 64;
    const int tid = threadIdx.x;
    const int tx = tid & 15, ty = tid >> 4;

    const bool isA = tid < 128;
    const int st = isA ? tid : tid - 128;
    const int srow = st >> 1, sc4 = (st & 1) * 4;
    const float* Sptr = isA ? A + (size_t)(bm + srow)*DIM + sc4
                            : W + (size_t)(bn + srow)*DIM + sc4;

    float acc[4][4];
    #pragma unroll
    for (int i = 0; i < 4; ++i)
        #pragma unroll
        for (int j = 0; j < 4; ++j) acc[i][j] = 0.f;

    const int nt = DIM >> 3;  // 128
    float4 sreg = *(const float4*)Sptr;
    #pragma unroll
    for (int j = 0; j < 4; ++j) {
        if (isA) As[0][sc4+j][srow] = (&sreg.x)[j];
        else     Ws[0][sc4+j][srow] = (&sreg.x)[j];
    }
    __syncthreads();

    for (int t = 0; t < nt; ++t) {
        const int cur = t & 1;
        if (t + 1 < nt) sreg = *(const float4*)(Sptr + (t+1)*8);
        #pragma unroll
        for (int kk = 0; kk < 8; ++kk) {
            float4 a4 = *(const float4*)&As[cur][kk][ty*4];
            float4 b4 = *(const float4*)&Ws[cur][kk][tx*4];
            const float* a = &a4.x;
            const float* b = &b4.x;
            #pragma unroll
            for (int i = 0; i < 4; ++i)
                #pragma unroll
                for (int j = 0; j < 4; ++j)
                    acc[i][j] += a[i]*b[j];
        }
        if (t + 1 < nt) {
            const int nxt = cur ^ 1;
            #pragma unroll
            for (int j = 0; j < 4; ++j) {
                if (isA) As[nxt][sc4+j][srow] = (&sreg.x)[j];
                else     Ws[nxt][sc4+j][srow] = (&sreg.x)[j];
            }
        }
        __syncthreads();
    }

    #pragma unroll
    for (int i = 0; i < 4; ++i) {
        int row = bm + ty*4 + i;
        int col = bn + tx*4;
        float4 o;
        o.x = acc[i][0] + bias[col];
        o.y = acc[i][1] + bias[col+1];
        o.z = acc[i][2] + bias[col+2];
        o.w = acc[i][3] + bias[col+3];
        *(float4*)&C[(size_t)row*PROJ + col] = o;
    }
}

// ---------------- fp16 mma helpers ----------------
__device__ __forceinline__ unsigned pack_h2(float lo, float hi) {
    __half2 h = __floats2half2_rn(lo, hi);
    return *(unsigned*)&h;
}
__device__ __forceinline__ void mma_f16(float c[4],
    unsigned a0, unsigned a1, unsigned a2, unsigned a3,
    unsigned b0, unsigned b1)
{
    asm("mma.sync.aligned.m16n8k16.row.col.f32.f16.f16.f32 "
        "{%0,%1,%2,%3},{%4,%5,%6,%7},{%8,%9},{%0,%1,%2,%3};"
        : "+f"(c[0]), "+f"(c[1]), "+f"(c[2]), "+f"(c[3])
        : "r"(a0), "r"(a1), "r"(a2), "r"(a3), "r"(b0), "r"(b1));
}

// ---------------- 512-thread fp16 GEMM core: 128x128 tile, BK=16 ----------
// A[M,K] row-major fp32, W[N,K] row-major fp32 (B^T), C row-major fp32.
// smem holds half2 k-pairs: As[kk][m] = {A[m][2kk], A[m][2kk+1]}.
__device__ __forceinline__ void tc512h_core(
    const float* __restrict__ A, const float* __restrict__ W,
    const float* __restrict__ bias, float* __restrict__ C,
    int K, int ldc, int bm, int bn)
{
    __shared__ unsigned As[2][8][136];
    __shared__ unsigned Ws[2][8][136];

    const int tid = threadIdx.x;
    const int w = tid >> 5, lane = tid & 31;
    const int wm = w >> 2, wn = w & 3;          // 4x4 warp grid, 32x32 tiles
    const int qr = lane >> 2, qc = lane & 3;

    const bool isA = tid < 256;
    const int st = isA ? tid : tid - 256;
    const int srow = st >> 1, sk8 = (st & 1) * 8, skk = (st & 1) * 4;
    const float* Sptr = isA ? A + (size_t)(bm + srow)*K + sk8
                            : W + (size_t)(bn + srow)*K + sk8;

    float acc[2][4][4];
    #pragma unroll
    for (int i = 0; i < 2; ++i)
        #pragma unroll
        for (int j = 0; j < 4; ++j)
            #pragma unroll
            for (int r = 0; r < 4; ++r) acc[i][j][r] = 0.f;

    const int nt = K >> 4;
    float4 s0 = *(const float4*)Sptr;
    float4 s1 = *(const float4*)(Sptr + 4);
    {
        unsigned p0 = pack_h2(s0.x, s0.y), p1 = pack_h2(s0.z, s0.w);
        unsigned p2 = pack_h2(s1.x, s1.y), p3 = pack_h2(s1.z, s1.w);
        if (isA) { As[0][skk][srow]=p0; As[0][skk+1][srow]=p1; As[0][skk+2][srow]=p2; As[0][skk+3][srow]=p3; }
        else     { Ws[0][skk][srow]=p0; Ws[0][skk+1][srow]=p1; Ws[0][skk+2][srow]=p2; Ws[0][skk+3][srow]=p3; }
    }
    __syncthreads();

    for (int t = 0; t < nt; ++t) {
        const int cur = t & 1;
        if (t + 1 < nt) {
            s0 = *(const float4*)(Sptr + (t+1)*16);
            s1 = *(const float4*)(Sptr + (t+1)*16 + 4);
        }
        unsigned af[2][4], bf[4][2];
        #pragma unroll
        for (int i = 0; i < 2; ++i) {
            int m0 = wm*32 + i*16 + qr;
            af[i][0] = As[cur][qc  ][m0];
            af[i][1] = As[cur][qc  ][m0+8];
            af[i][2] = As[cur][qc+4][m0];
            af[i][3] = As[cur][qc+4][m0+8];
        }
        #pragma unroll
        for (int j = 0; j < 4; ++j) {
            int n0 = wn*32 + j*8 + qr;
            bf[j][0] = Ws[cur][qc  ][n0];
            bf[j][1] = Ws[cur][qc+4][n0];
        }
        #pragma unroll
        for (int i = 0; i < 2; ++i)
            #pragma unroll
            for (int j = 0; j < 4; ++j)
                mma_f16(acc[i][j], af[i][0], af[i][1], af[i][2], af[i][3],
                        bf[j][0], bf[j][1]);
        if (t + 1 < nt) {
            const int nxt = cur ^ 1;
            unsigned p0 = pack_h2(s0.x, s0.y), p1 = pack_h2(s0.z, s0.w);
            unsigned p2 = pack_h2(s1.x, s1.y), p3 = pack_h2(s1.z, s1.w);
            if (isA) { As[nxt][skk][srow]=p0; As[nxt][skk+1][srow]=p1; As[nxt][skk+2][srow]=p2; As[nxt][skk+3][srow]=p3; }
            else     { Ws[nxt][skk][srow]=p0; Ws[nxt][skk+1][srow]=p1; Ws[nxt][skk+2][srow]=p2; Ws[nxt][skk+3][srow]=p3; }
        }
        __syncthreads();
    }

    #pragma unroll
    for (int i = 0; i < 2; ++i) {
        int r0 = bm + wm*32 + i*16 + qr;
        #pragma unroll
        for (int j = 0; j < 4; ++j) {
            int c0 = bn + wn*32 + j*8 + 2*qc;
            float bx = 0.f, by = 0.f;
            if (bias) { bx = bias[c0]; by = bias[c0+1]; }
            float2 o0, o1;
            o0.x = acc[i][j][0] + bx; o0.y = acc[i][j][1] + by;
            o1.x = acc[i][j][2] + bx; o1.y = acc[i][j][3] + by;
            *(float2*)&C[(size_t)r0*ldc + c0]     = o0;
            *(float2*)&C[(size_t)(r0+8)*ldc + c0] = o1;
        }
    }
}

// out-proj: C[2048,1024] = cat * out_w^T + out_b
__global__ __launch_bounds__(512) void gemm_tc512(
    const float* __restrict__ A, const float* __restrict__ W,
    const float* __restrict__ bias, float* __restrict__ C,
    int K, int ldc)
{
    tc512h_core(A, W, bias, C, K, ldc, blockIdx.y*128, blockIdx.x*128);
}

// V projection per head (z selects head weight), strided output into g_Vp
__global__ __launch_bounds__(512) void gemm_tcv512(
    const float* __restrict__ V,
    const float* __restrict__ w0, const float* __restrict__ w1,
    const float* __restrict__ w2, const float* __restrict__ w3,
    float* __restrict__ C)
{
    const float* W = (blockIdx.z == 0) ? w0 : (blockIdx.z == 1) ? w1
                   : (blockIdx.z == 2) ? w2 : w3;
    tc512h_core(V, W, nullptr, C + blockIdx.z*HDIM,
                DIM, 4*HDIM, blockIdx.y*128, blockIdx.x*128);
}

// ---------------- PV GEMM, fp16 mma, fused exp weighting ------------------
__global__ __launch_bounds__(512) void gemm_pv512()
{
    __shared__ unsigned As[2][8][136];
    __shared__ unsigned Ws[2][8][136];

    const int bh = blockIdx.z, b = bh >> 2, head = bh & 3;
    const int bm = blockIdx.y * 128, bn = blockIdx.x * 128;
    const int tid = threadIdx.x;
    const int w = tid >> 5, lane = tid & 31;
    const int wm = w >> 2, wn = w & 3;
    const int qr = lane >> 2, qc = lane & 3;

    const bool isA = tid < 256;
    const int st = isA ? tid : tid - 256;
    // A: S rows, exp-weighted; thread covers k-chunk of 8 (pair slots skk..skk+3)
    const int lrow = st >> 1, sk8 = (st & 1) * 8, skk = (st & 1) * 4;
    const float* Aptr = g_S + ((size_t)bh << 20) + (size_t)(bm + lrow)*1024 + sk8;
    const float mrow  = g_m [bh*1024 + bm + lrow];
    const float ilrow = g_il[bh*1024 + bm + lrow];
    // W: Vp row-pairs (2kq, 2kq+1), 4 cols per thread
    const int kq = st >> 5, n4 = st & 31;
    const float* Wptr = g_Vp + (size_t)(b*SEQ + 2*kq)*1024 + head*HDIM + bn + n4*4;

    float acc[2][4][4];
    #pragma unroll
    for (int i = 0; i < 2; ++i)
        #pragma unroll
        for (int j = 0; j < 4; ++j)
            #pragma unroll
            for (int r = 0; r < 4; ++r) acc[i][j][r] = 0.f;

    const int nt = 64;   // K=1024, BK=16
    float4 s0, s1;
    if (isA) {
        s0 = *(const float4*)Aptr;
        s1 = *(const float4*)(Aptr + 4);
        float p[8];
        #pragma unroll
        for (int j = 0; j < 4; ++j) {
            p[j]   = __expf((&s0.x)[j] - mrow) * ilrow;
            p[4+j] = __expf((&s1.x)[j] - mrow) * ilrow;
        }
        #pragma unroll
        for (int j = 0; j < 4; ++j)
            As[0][skk+j][lrow] = pack_h2(p[2*j], p[2*j+1]);
    } else {
        s0 = *(const float4*)Wptr;           // row 2kq
        s1 = *(const float4*)(Wptr + 1024);  // row 2kq+1
        #pragma unroll
        for (int j = 0; j < 4; ++j)
            Ws[0][kq][n4*4+j] = pack_h2((&s0.x)[j], (&s1.x)[j]);
    }
    __syncthreads();

    for (int t = 0; t < nt; ++t) {
        const int cur = t & 1;
        if (t + 1 < nt) {
            if (isA) {
                s0 = *(const float4*)(Aptr + (t+1)*16);
                s1 = *(const float4*)(Aptr + (t+1)*16 + 4);
            } else {
                s0 = *(const float4*)(Wptr + (size_t)(t+1)*16*1024);
                s1 = *(const float4*)(Wptr + (size_t)(t+1)*16*1024 + 1024);
            }
        }
        unsigned af[2][4], bf[4][2];
        #pragma unroll
        for (int i = 0; i < 2; ++i) {
            int m0 = wm*32 + i*16 + qr;
            af[i][0] = As[cur][qc  ][m0];
            af[i][1] = As[cur][qc  ][m0+8];
            af[i][2] = As[cur][qc+4][m0];
            af[i][3] = As[cur][qc+4][m0+8];
        }
        #pragma unroll
        for (int j = 0; j < 4; ++j) {
            int n0 = wn*32 + j*8 + qr;
            bf[j][0] = Ws[cur][qc  ][n0];
            bf[j][1] = Ws[cur][qc+4][n0];
        }
        #pragma unroll
        for (int i = 0; i < 2; ++i)
            #pragma unroll
            for (int j = 0; j < 4; ++j)
                mma_f16(acc[i][j], af[i][0], af[i][1], af[i][2], af[i][3],
                        bf[j][0], bf[j][1]);
        if (t + 1 < nt) {
            const int nxt = cur ^ 1;
            if (isA) {
                float p[8];
                #pragma unroll
                for (int j = 0; j < 4; ++j) {
                    p[j]   = __expf((&s0.x)[j] - mrow) * ilrow;
                    p[4+j] = __expf((&s1.x)[j] - mrow) * ilrow;
                }
                #pragma unroll
                for (int j = 0; j < 4; ++j)
                    As[nxt][skk+j][lrow] = pack_h2(p[2*j], p[2*j+1]);
            } else {
                #pragma unroll
                for (int j = 0; j < 4; ++j)
                    Ws[nxt][kq][n4*4+j] = pack_h2((&s0.x)[j], (&s1.x)[j]);
            }
        }
        __syncthreads();
    }

    float* Cb = g_cat + (size_t)(b*SEQ)*1024 + head*HDIM;
    #pragma unroll
    for (int i = 0; i < 2; ++i) {
        int r0 = bm + wm*32 + i*16 + qr;
        #pragma unroll
        for (int j = 0; j < 4; ++j) {
            int c0 = bn + wn*32 + j*8 + 2*qc;
            float2 o0, o1;
            o0.x = acc[i][j][0]; o0.y = acc[i][j][1];
            o1.x = acc[i][j][2]; o1.y = acc[i][j][3];
            *(float2*)&Cb[(size_t)r0*1024 + c0]     = o0;
            *(float2*)&Cb[(size_t)(r0+8)*1024 + c0] = o1;
        }
    }
}

// ---------------- bit packing for boolean heads ----------------
__global__ void pack_bits()
{
    int gw = (blockIdx.x * blockDim.x + threadIdx.x) >> 5;
    int lane = threadIdx.x & 31;
    if (gw >= NTOK) return;
    unsigned q0 = __ballot_sync(0xffffffffu, g_qproj[(size_t)gw*PROJ + lane]       > 0.f);
    unsigned q1 = __ballot_sync(0xffffffffu, g_qproj[(size_t)gw*PROJ + 96 + lane]  > 0.f);
    unsigned k0 = __ballot_sync(0xffffffffu, g_kproj[(size_t)gw*PROJ + lane]       > 0.f);
    unsigned k1 = __ballot_sync(0xffffffffu, g_kproj[(size_t)gw*PROJ + 96 + lane]  > 0.f);
    if (lane == 0) {
        g_qbits[gw*2]   = q0; g_qbits[gw*2+1] = q1;
        g_kbits[gw*2]   = k0; g_kbits[gw*2+1] = k1;
    }
}

// ---------------- stage 1: scores (massively parallel, 64q x 64k tiles) ----
#define RE_STRIDE 34
#define TR_STRIDE 17

__global__ __launch_bounds__(256) void scores_kernel(
    const float* __restrict__ t_temp, const float* __restrict__ p_fusion)
{
    __shared__ float    qer[64*RE_STRIDE];
    __shared__ float    ker[64*RE_STRIDE];
    __shared__ __half2  qet[64*TR_STRIDE];
    __shared__ __half2  ket[64*TR_STRIDE];
    __shared__ unsigned qb[64], kb[64];

    const int k0  = blockIdx.x * 64;
    const int n0  = blockIdx.y * 64;
    const int bh  = blockIdx.z;
    const int b   = bh >> 2, head = bh & 3;
    const int tid = threadIdx.x;

    float inv_sp = 1.f;
    if (head == 1) inv_sp = 1.f / log1pf(expf(t_temp[0]));
    float fw0 = 0.f, fw1 = 0.f, fw2 = 0.f;
    if (head == 3) {
        float p0 = p_fusion[0], p1 = p_fusion[1], p2 = p_fusion[2];
        float mx = fmaxf(p0, fmaxf(p1, p2));
        float e0 = expf(p0-mx), e1 = expf(p1-mx), e2 = expf(p2-mx);
        float inv = 1.f/(e0+e1+e2);
        fw0 = e0*inv; fw1 = e1*inv; fw2 = e2*inv;
    }

    if (head == 0) {
        if (tid < 64)       qb[tid]    = g_qbits[(b*SEQ + n0 + tid)*2];
        else if (tid < 128) kb[tid-64] = g_kbits[(b*SEQ + k0 + tid-64)*2];
    } else if (head == 1) {
        for (int j = tid; j < 1024; j += 256) {
            int t = j >> 4, m = j & 15;
            const float* bq_ = &g_qproj[(size_t)(b*SEQ + n0 + t)*PROJ];
            const float* bk_ = &g_kproj[(size_t)(b*SEQ + k0 + t)*PROJ];
            qet[t*TR_STRIDE+m] = __floats2half2_rn(bq_[32+2*m], bq_[33+2*m]);
            ket[t*TR_STRIDE+m] = __floats2half2_rn(bk_[32+2*m], bk_[33+2*m]);
        }
    } else if (head == 2) {
        for (int j = tid; j < 2048; j += 256) {
            int t = j >> 5, m = j & 31;
            qer[t*RE_STRIDE+m] = g_qproj[(size_t)(b*SEQ + n0 + t)*PROJ + 64 + m];
            ker[t*RE_STRIDE+m] = g_kproj[(size_t)(b*SEQ + k0 + t)*PROJ + 64 + m];
        }
    } else {
        if (tid < 64)       qb[tid]    = g_qbits[(b*SEQ + n0 + tid)*2 + 1];
        else if (tid < 128) kb[tid-64] = g_kbits[(b*SEQ + k0 + tid-64)*2 + 1];
        for (int j = tid; j < 1024; j += 256) {
            int t = j >> 4, m = j & 15;
            const float* bq_ = &g_qproj[(size_t)(b*SEQ + n0 + t)*PROJ];
            const float* bk_ = &g_kproj[(size_t)(b*SEQ + k0 + t)*PROJ];
            qet[t*TR_STRIDE+m] = __floats2half2_rn(bq_[128+2*m], bq_[129+2*m]);
            ket[t*TR_STRIDE+m] = __floats2half2_rn(bk_[128+2*m], bk_[129+2*m]);
        }
        for (int j = tid; j < 2048; j += 256) {
            int t = j >> 5, m = j & 31;
            qer[t*RE_STRIDE+m] = g_qproj[(size_t)(b*SEQ + n0 + t)*PROJ + 160 + m];
            ker[t*RE_STRIDE+m] = g_kproj[(size_t)(b*SEQ + k0 + t)*PROJ + 160 + m];
        }
    }
    __syncthreads();

    const int kk    = tid & 63;
    const int qbase = (tid >> 6) * 16;
    float* Sout = g_S + ((size_t)bh << 20) + (size_t)(n0 + qbase)*1024 + k0 + kk;

    if (head == 0) {
        unsigned kr = kb[kk];
        #pragma unroll
        for (int i = 0; i < 16; ++i) {
            int p = __popc(qb[qbase+i] ^ kr);
            Sout[(size_t)i*1024] = (1.f - p*(1.f/32.f)) * SCALEF;
        }
    } else if (head == 1) {
        __half2 kr[16];
        const __half2* krow = &ket[kk*TR_STRIDE];
        #pragma unroll
        for (int m = 0; m < 16; ++m) kr[m] = krow[m];
        #pragma unroll 4
        for (int i = 0; i < 16; ++i) {
            const __half2* qe = &qet[(qbase+i)*TR_STRIDE];
            __half2 mnA = __hadd2(qe[0], kr[0]);
            __half2 mnB = __hadd2(qe[1], kr[1]);
            #pragma unroll
            for (int m = 2; m < 16; m += 2) {
                mnA = __hmin2(mnA, __hadd2(qe[m],   kr[m]));
                mnB = __hmin2(mnB, __hadd2(qe[m+1], kr[m+1]));
            }
            __half2 mn = __hmin2(mnA, mnB);
            float mnf = fminf(__low2float(mn), __high2float(mn));
            Sout[(size_t)i*1024] = -mnf * inv_sp;
        }
    } else if (head == 2) {
        float krr[32];
        const float* krow = &ker[kk*RE_STRIDE];
        #pragma unroll
        for (int m = 0; m < 32; ++m) krr[m] = krow[m];
        #pragma unroll 4
        for (int i = 0; i < 16; ++i) {
            const float* qe = &qer[(qbase+i)*RE_STRIDE];
            float da = 0.f, db = 0.f;
            #pragma unroll
            for (int m = 0; m < 32; m += 2) {
                da = fmaf(qe[m],   krr[m],   da);
                db = fmaf(qe[m+1], krr[m+1], db);
            }
            Sout[(size_t)i*1024] = (da + db) * SCALEF;
        }
    } else {
        __half2 krt[16];
        float krr[32];
        const __half2* ktrow = &ket[kk*TR_STRIDE];
        const float* krrow = &ker[kk*RE_STRIDE];
        #pragma unroll
        for (int m = 0; m < 16; ++m) krt[m] = ktrow[m];
        #pragma unroll
        for (int m = 0; m < 32; ++m) krr[m] = krrow[m];
        unsigned kr = kb[kk];
        #pragma unroll 2
        for (int i = 0; i < 16; ++i) {
            const __half2* qe = &qet[(qbase+i)*TR_STRIDE];
            const float* qf  = &qer[(qbase+i)*RE_STRIDE];
            __half2 mnA = __hadd2(qe[0], krt[0]);
            __half2 mnB = __hadd2(qe[1], krt[1]);
            float da = 0.f, db = 0.f;
            #pragma unroll
            for (int m = 2; m < 16; m += 2) {
                mnA = __hmin2(mnA, __hadd2(qe[m],   krt[m]));
                mnB = __hmin2(mnB, __hadd2(qe[m+1], krt[m+1]));
            }
            #pragma unroll
            for (int m = 0; m < 32; m += 2) {
                da = fmaf(qf[m],   krr[m],   da);
                db = fmaf(qf[m+1], krr[m+1], db);
            }
            __half2 mn = __hmin2(mnA, mnB);
            float mnf = fminf(__low2float(mn), __high2float(mn));
            float simb = 1.f - __popc(qb[qbase+i] ^ kr)*(1.f/32.f);
            Sout[(size_t)i*1024] = (fw0*simb - fw1*mnf + fw2*(da + db)) * SCALEF;
        }
    }
}

// ---------------- stage 2: row softmax stats (1 warp / row) ----------------
__device__ __forceinline__ float wredmax(float v) {
    #pragma unroll
    for (int o = 16; o; o >>= 1) v = fmaxf(v, __shfl_xor_sync(0xffffffffu, v, o));
    return v;
}
__device__ __forceinline__ float wredsum(float v) {
    #pragma unroll
    for (int o = 16; o; o >>= 1) v += __shfl_xor_sync(0xffffffffu, v, o);
    return v;
}

__global__ __launch_bounds__(256) void stats_kernel()
{
    int gw   = (blockIdx.x * blockDim.x + threadIdx.x) >> 5;  // row 0..8191
    int lane = threadIdx.x & 31;
    const float4* srow = (const float4*)(g_S + ((size_t)gw << 10));
    float4 v[8];
    float mx = -INFINITY;
    #pragma unroll
    for (int j = 0; j < 8; ++j) {
        v[j] = srow[j*32 + lane];
        mx = fmaxf(mx, fmaxf(fmaxf(v[j].x, v[j].y), fmaxf(v[j].z, v[j].w)));
    }
    mx = wredmax(mx);
    float s = 0.f;
    #pragma unroll
    for (int j = 0; j < 8; ++j)
        s += __expf(v[j].x-mx) + __expf(v[j].y-mx) + __expf(v[j].z-mx) + __expf(v[j].w-mx);
    s = wredsum(s);
    if (lane == 0) { g_m[gw] = mx; g_il[gw] = 1.f/s; }
}

// ---------------- host launch ----------------
extern "C" void kernel_launch(void* const* d_in, const int* in_sizes, int n_in,
                              void* d_out, int out_size)
{
    const float* Q        = (const float*)d_in[0];
    const float* K        = (const float*)d_in[1];
    const float* V        = (const float*)d_in[2];
    const float* bq_w     = (const float*)d_in[3];
    const float* bq_b     = (const float*)d_in[4];
    const float* bk_w     = (const float*)d_in[5];
    const float* bk_b     = (const float*)d_in[6];
    const float* b_v      = (const float*)d_in[7];
    const float* tq_w     = (const float*)d_in[8];
    const float* tq_b     = (const float*)d_in[9];
    const float* tk_w     = (const float*)d_in[10];
    const float* tk_b     = (const float*)d_in[11];
    const float* t_v      = (const float*)d_in[12];
    const float* t_temp   = (const float*)d_in[13];
    const float* rq_w     = (const float*)d_in[14];
    const float* rq_b     = (const float*)d_in[15];
    const float* rk_w     = (const float*)d_in[16];
    const float* rk_b     = (const float*)d_in[17];
    const float* r_v      = (const float*)d_in[18];
    const float* pq_w     = (const float*)d_in[19];
    const float* pq_b     = (const float*)d_in[20];
    const float* pk_w     = (const float*)d_in[21];
    const float* pk_b     = (const float*)d_in[22];
    const float* p_v      = (const float*)d_in[23];
    const float* p_fusion = (const float*)d_in[24];
    const float* out_w    = (const float*)d_in[25];
    const float* out_b    = (const float*)d_in[26];
    float* out = (float*)d_out;

    void *pVp, *pcat;
    cudaGetSymbolAddress(&pVp,  g_Vp);
    cudaGetSymbolAddress(&pcat, g_cat);

    pack_weights<<<128, 256>>>(bq_w, tq_w, rq_w, pq_w, bq_b, tq_b, rq_b, pq_b,
                               bk_w, tk_w, rk_w, pk_w, bk_b, tk_b, rk_b, pk_b);

    // Q/K projections (exact fp32): 64x64 tiles, grid 192
    gemm_qk<<<dim3(3, 32, 2), 256>>>(Q, K);

    // V projection (fp16 tensor cores, per head via z; strided into g_Vp)
    gemm_tcv512<<<dim3(2, 16, 4), 512>>>(V, b_v, t_v, r_v, p_v, (float*)pVp);

    pack_bits<<<NTOK*32/256, 256>>>();

    // stage 1: all scores
    scores_kernel<<<dim3(16, 16, 8), 256>>>(t_temp, p_fusion);

    // stage 2: exact softmax stats
    stats_kernel<<<1024, 256>>>();

    // stage 3: exp-weighted PV fp16 tensor-core GEMM -> g_cat
    gemm_pv512<<<dim3(2, 8, 8), 512>>>();

    // output projection (fp16 tensor cores)
    gemm_tc512<<<dim3(8, 16), 512>>>((const float*)pcat, out_w, out_b,
                                     out, DIM, DIM);
}